// round 1
// baseline (speedup 1.0000x reference)
#include <cuda_runtime.h>
#include <math.h>

// ---------------------------------------------------------------------------
// Problem constants
// ---------------------------------------------------------------------------
#define NG    8       // groups
#define NC    256     // channels (DIM)
#define NL    4096    // sequence length (64*64)
#define NST   8       // D_STATE
#define NRK   16      // DT_RANK
#define NEDBL 32      // DT_RANK + 2*D_STATE
#define NCHUNK 16
#define CHUNK  256    // NL / NCHUNK
#define NDEPTH 4

// ---------------------------------------------------------------------------
// Scratch (device globals; no allocation allowed)
// ---------------------------------------------------------------------------
__device__ float g_x   [NG * NL * NC];          // (g, l, c) current residual stream
__device__ float g_xn  [NG * NL * NC];          // (g, l, c) layernormed
__device__ float g_xx  [NG * NC * NL];          // (g, d, l) xx half of in_proj
__device__ float g_z   [NG * NC * NL];          // (g, d, l) z half of in_proj
__device__ float g_xc  [2 * NG * NC * NL];      // (dir, g, d, l) conv+silu
__device__ float g_xdbl[2 * NG * NEDBL * NL];   // (dir, g, e, l) dt|B|C
__device__ float g_delta[2 * NG * NC * NL];     // (dir, g, d, l)
__device__ float g_y   [NG * NC * NL];          // (g, d, l) merged scan output
__device__ float g_gl  [NG * NL * NC];          // (g, l, o) out_proj output
__device__ float g_ap  [2 * NG * NC * NCHUNK * NST];
__device__ float g_hend[2 * NG * NC * NCHUNK * NST];
__device__ float g_hin [2 * NG * NC * NCHUNK * NST];

// ---------------------------------------------------------------------------
// 1. Segment mean + transpose (G*A, C, L) -> g_x (g, l, c)
// ---------------------------------------------------------------------------
__global__ void __launch_bounds__(256) mean_kernel(const float* __restrict__ data,
                                                   const int* __restrict__ rl) {
    __shared__ float tile[32][33];
    int g  = blockIdx.z;
    int c0 = blockIdx.y * 32;
    int l0 = blockIdx.x * 32;
    int start = 0;
    for (int gg = 0; gg < g; gg++) start += rl[gg];
    int cnt = rl[g];
    float inv = 1.0f / (float)cnt;
    int tx = threadIdx.x;
    for (int r = threadIdx.y; r < 32; r += 8) {
        float s = 0.0f;
        for (int a = 0; a < cnt; a++)
            s += data[((size_t)(start + a) * NC + (c0 + r)) * NL + l0 + tx];
        tile[r][tx] = s * inv;
    }
    __syncthreads();
    for (int r = threadIdx.y; r < 32; r += 8)
        g_x[((size_t)g * NL + (l0 + r)) * NC + c0 + tx] = tile[tx][r];
}

// ---------------------------------------------------------------------------
// Block reduce helper for LayerNorm (256 threads / row)
// ---------------------------------------------------------------------------
__device__ __forceinline__ void row_stats(float v, float& mu, float& rstd,
                                          float* sh) {
    float s = v, s2 = v * v;
    #pragma unroll
    for (int off = 16; off; off >>= 1) {
        s  += __shfl_down_sync(0xffffffffu, s, off);
        s2 += __shfl_down_sync(0xffffffffu, s2, off);
    }
    int lane = threadIdx.x & 31, wid = threadIdx.x >> 5;
    if (lane == 0) { sh[wid] = s; sh[8 + wid] = s2; }
    __syncthreads();
    if (threadIdx.x == 0) {
        float S = 0.f, S2 = 0.f;
        #pragma unroll
        for (int i = 0; i < 8; i++) { S += sh[i]; S2 += sh[8 + i]; }
        float m = S * (1.0f / NC);
        float var = S2 * (1.0f / NC) - m * m;
        sh[16] = m;
        sh[17] = rsqrtf(var + 1e-5f);
    }
    __syncthreads();
    mu = sh[16]; rstd = sh[17];
}

// LN: g_x -> g_xn
__global__ void __launch_bounds__(256) ln1_kernel(const float* __restrict__ w,
                                                  const float* __restrict__ b) {
    __shared__ float sh[18];
    size_t row = blockIdx.x;
    int c = threadIdx.x;
    float v = g_x[row * NC + c];
    float mu, rstd;
    row_stats(v, mu, rstd, sh);
    g_xn[row * NC + c] = (v - mu) * rstd * w[c] + b[c];
}

// LN(g_gl) + residual(g_x) -> g_x
__global__ void __launch_bounds__(256) ln2_kernel(const float* __restrict__ w,
                                                  const float* __restrict__ b) {
    __shared__ float sh[18];
    size_t row = blockIdx.x;
    int c = threadIdx.x;
    float v = g_gl[row * NC + c];
    float mu, rstd;
    row_stats(v, mu, rstd, sh);
    float skip = g_x[row * NC + c];
    g_x[row * NC + c] = (v - mu) * rstd * w[c] + b[c] + skip;
}

// ---------------------------------------------------------------------------
// 2. in_proj GEMM: xz[g,e,l] = sum_c g_xn[g,l,c] * W[e,c]
//    A row-major [M=l][K=c]; B [N=e][K=c]; C written [e][l] split xx/z.
//    Tile BM=128(l) x BN=64(e) x BK=16, 256 threads, 8x4 per thread.
// ---------------------------------------------------------------------------
__global__ void __launch_bounds__(256) gemm_in_kernel(const float* __restrict__ W) {
    __shared__ float As[16][132];
    __shared__ float Bs[16][68];
    const int l0 = blockIdx.x * 128;
    const int e0 = blockIdx.y * 64;
    const int g  = blockIdx.z;
    const int tid = threadIdx.x;
    const int tx = tid & 15, ty = tid >> 4;
    const int lb = tx * 8, eb = ty * 4;
    float acc[4][8];
    #pragma unroll
    for (int j = 0; j < 4; j++)
        #pragma unroll
        for (int i = 0; i < 8; i++) acc[j][i] = 0.0f;
    const float* A = g_xn + (size_t)g * NL * NC;
    for (int k0 = 0; k0 < NC; k0 += 16) {
        #pragma unroll
        for (int it = 0; it < 2; it++) {
            int t = tid + it * 256;
            int row = t >> 2, cq = t & 3;
            float4 v = *reinterpret_cast<const float4*>(A + (size_t)(l0 + row) * NC + k0 + cq * 4);
            As[cq * 4 + 0][row] = v.x; As[cq * 4 + 1][row] = v.y;
            As[cq * 4 + 2][row] = v.z; As[cq * 4 + 3][row] = v.w;
        }
        {
            int row = tid >> 2, cq = tid & 3;
            float4 v = *reinterpret_cast<const float4*>(W + (size_t)(e0 + row) * NC + k0 + cq * 4);
            Bs[cq * 4 + 0][row] = v.x; Bs[cq * 4 + 1][row] = v.y;
            Bs[cq * 4 + 2][row] = v.z; Bs[cq * 4 + 3][row] = v.w;
        }
        __syncthreads();
        #pragma unroll
        for (int k = 0; k < 16; k++) {
            float4 a0 = *reinterpret_cast<const float4*>(&As[k][lb]);
            float4 a1 = *reinterpret_cast<const float4*>(&As[k][lb + 4]);
            float4 bq = *reinterpret_cast<const float4*>(&Bs[k][eb]);
            float av[8] = {a0.x, a0.y, a0.z, a0.w, a1.x, a1.y, a1.z, a1.w};
            float bv[4] = {bq.x, bq.y, bq.z, bq.w};
            #pragma unroll
            for (int j = 0; j < 4; j++)
                #pragma unroll
                for (int i = 0; i < 8; i++)
                    acc[j][i] = fmaf(av[i], bv[j], acc[j][i]);
        }
        __syncthreads();
    }
    #pragma unroll
    for (int j = 0; j < 4; j++) {
        int e = e0 + eb + j;
        float* dst;
        if (e < NC) dst = g_xx + (((size_t)g * NC + e) << 12) + l0 + lb;
        else        dst = g_z  + (((size_t)g * NC + (e - NC)) << 12) + l0 + lb;
        float4 v0 = {acc[j][0], acc[j][1], acc[j][2], acc[j][3]};
        float4 v1 = {acc[j][4], acc[j][5], acc[j][6], acc[j][7]};
        *reinterpret_cast<float4*>(dst)     = v0;
        *reinterpret_cast<float4*>(dst + 4) = v1;
    }
}

// ---------------------------------------------------------------------------
// 3. causal depthwise conv (k=4) + SiLU, both directions.
//    dir=1 operates on the flipped sequence.
// ---------------------------------------------------------------------------
__global__ void __launch_bounds__(256) conv_silu_kernel(const float* __restrict__ cw,
                                                        const float* __restrict__ cb) {
    int idx = blockIdx.x * 256 + threadIdx.x;          // 2*8*256*4096
    int l   = idx & (NL - 1);
    int d   = (idx >> 12) & (NC - 1);
    int g   = (idx >> 20) & 7;
    int dir = idx >> 23;
    const float* X = g_xx + ((size_t)(g * NC + d) << 12);
    float s = cb[d];
    #pragma unroll
    for (int j = 0; j < 4; j++) {
        int lj = l - 3 + j;
        if (lj >= 0) {
            int src = dir ? (NL - 1 - lj) : lj;
            s = fmaf(cw[d * 4 + j], X[src], s);
        }
    }
    float sig = 1.0f / (1.0f + __expf(-s));
    g_xc[((size_t)(dir * NG + g) * NC + d) * NL + l] = s * sig;
}

// ---------------------------------------------------------------------------
// 4. x_proj GEMM: xdbl[dg,e,l] = sum_d g_xc[dg,d,l] * W[e,d]
//    A is [K=d][M=l] (l contiguous). BM=256(l), BN=32(e), BK=16.
// ---------------------------------------------------------------------------
__global__ void __launch_bounds__(256) gemm_xproj_kernel(const float* __restrict__ W) {
    __shared__ float As[16][260];
    __shared__ float Bs[16][36];
    const int l0 = blockIdx.x * 256;
    const int dg = blockIdx.y;      // dir*8 + g
    const int tid = threadIdx.x;
    const int tx = tid & 31, ty = tid >> 5;
    const int lb = tx * 8, eb = ty * 4;
    float acc[4][8];
    #pragma unroll
    for (int j = 0; j < 4; j++)
        #pragma unroll
        for (int i = 0; i < 8; i++) acc[j][i] = 0.0f;
    const float* A = g_xc + (size_t)dg * NC * NL;
    for (int k0 = 0; k0 < NC; k0 += 16) {
        #pragma unroll
        for (int it = 0; it < 4; it++) {
            int t = tid + it * 256;
            int row = t >> 6, lq = t & 63;
            float4 v = *reinterpret_cast<const float4*>(A + (size_t)(k0 + row) * NL + l0 + lq * 4);
            *reinterpret_cast<float4*>(&As[row][lq * 4]) = v;
        }
        if (tid < 128) {
            int row = tid >> 2, cq = tid & 3;
            float4 v = *reinterpret_cast<const float4*>(W + (size_t)row * NC + k0 + cq * 4);
            Bs[cq * 4 + 0][row] = v.x; Bs[cq * 4 + 1][row] = v.y;
            Bs[cq * 4 + 2][row] = v.z; Bs[cq * 4 + 3][row] = v.w;
        }
        __syncthreads();
        #pragma unroll
        for (int k = 0; k < 16; k++) {
            float4 a0 = *reinterpret_cast<const float4*>(&As[k][lb]);
            float4 a1 = *reinterpret_cast<const float4*>(&As[k][lb + 4]);
            float4 bq = *reinterpret_cast<const float4*>(&Bs[k][eb]);
            float av[8] = {a0.x, a0.y, a0.z, a0.w, a1.x, a1.y, a1.z, a1.w};
            float bv[4] = {bq.x, bq.y, bq.z, bq.w};
            #pragma unroll
            for (int j = 0; j < 4; j++)
                #pragma unroll
                for (int i = 0; i < 8; i++)
                    acc[j][i] = fmaf(av[i], bv[j], acc[j][i]);
        }
        __syncthreads();
    }
    #pragma unroll
    for (int j = 0; j < 4; j++) {
        int e = eb + j;
        float* dst = g_xdbl + ((size_t)dg * NEDBL + e) * NL + l0 + lb;
        float4 v0 = {acc[j][0], acc[j][1], acc[j][2], acc[j][3]};
        float4 v1 = {acc[j][4], acc[j][5], acc[j][6], acc[j][7]};
        *reinterpret_cast<float4*>(dst)     = v0;
        *reinterpret_cast<float4*>(dst + 4) = v1;
    }
}

// ---------------------------------------------------------------------------
// 5. dt_proj + softplus: delta[dg,d,l] = softplus(sum_r W[d,r]*dt[dg,r,l] + b[d])
// ---------------------------------------------------------------------------
__global__ void __launch_bounds__(256) dtproj_kernel(const float* __restrict__ Wd,
                                                     const float* __restrict__ bias) {
    __shared__ float Ws[NC * NRK];
    __shared__ float bs[NC];
    const int l  = blockIdx.x * 256 + threadIdx.x;
    const int dg = blockIdx.y;
    for (int i = threadIdx.x; i < NC * NRK; i += 256) Ws[i] = Wd[i];
    bs[threadIdx.x] = bias[threadIdx.x];
    __syncthreads();
    float r[NRK];
    const float* dtp = g_xdbl + (size_t)dg * NEDBL * NL;
    #pragma unroll
    for (int rr = 0; rr < NRK; rr++) r[rr] = dtp[(size_t)rr * NL + l];
    float* out = g_delta + (size_t)dg * NC * NL + l;
    for (int d = 0; d < NC; d++) {
        float s = bs[d];
        #pragma unroll
        for (int rr = 0; rr < NRK; rr++) s = fmaf(Ws[d * NRK + rr], r[rr], s);
        float sp = (s > 20.0f) ? s : log1pf(__expf(s));
        out[(size_t)d * NL] = sp;
    }
}

// ---------------------------------------------------------------------------
// 6. selective scan, pass 1: per-chunk A-product and local end-state
// ---------------------------------------------------------------------------
__global__ void __launch_bounds__(256) scan_pass1_kernel(const float* __restrict__ AlogF,
                                                         const float* __restrict__ AlogB) {
    int idx = blockIdx.x * 256 + threadIdx.x;   // 65536: (dir,g,d,chunk)
    int ck  = idx & (NCHUNK - 1);
    int d   = (idx >> 4) & (NC - 1);
    int g   = (idx >> 12) & 7;
    int dir = idx >> 15;
    const float* Alog = (dir ? AlogB : AlogF) + d * NST;
    float A[NST];
    #pragma unroll
    for (int n = 0; n < NST; n++) A[n] = -__expf(Alog[n]);
    size_t base = ((size_t)(dir * NG + g) * NC + d) * NL + ck * CHUNK;
    const float* dp = g_delta + base;
    const float* up = g_xc + base;
    const float* Bp = g_xdbl + ((size_t)(dir * NG + g) * NEDBL + NRK) * NL + ck * CHUNK;
    float h[NST], ap[NST];
    #pragma unroll
    for (int n = 0; n < NST; n++) { h[n] = 0.0f; ap[n] = 1.0f; }
    for (int t = 0; t < CHUNK; t++) {
        float dl = dp[t];
        float du = dl * up[t];
        #pragma unroll
        for (int n = 0; n < NST; n++) {
            float a = __expf(dl * A[n]);
            ap[n] *= a;
            h[n] = fmaf(a, h[n], du * Bp[(size_t)n * NL + t]);
        }
    }
    size_t co = (size_t)idx * NST;
    #pragma unroll
    for (int n = 0; n < NST; n++) { g_ap[co + n] = ap[n]; g_hend[co + n] = h[n]; }
}

// sequential chunk combine (cheap): h_in per chunk
__global__ void __launch_bounds__(256) scan_combine_kernel() {
    int idx = blockIdx.x * 256 + threadIdx.x;   // 32768: (dir,g,d,n)
    int n   = idx & 7;
    int d   = (idx >> 3) & (NC - 1);
    int g   = (idx >> 11) & 7;
    int dir = idx >> 14;
    size_t base = (((size_t)(dir * NG + g) * NC + d) * NCHUNK) * NST + n;
    float h = 0.0f;
    for (int k = 0; k < NCHUNK; k++) {
        size_t o = base + (size_t)k * NST;
        g_hin[o] = h;
        h = g_ap[o] * h + g_hend[o];
    }
}

// pass 2: replay with known carry-in, emit gated output
__global__ void __launch_bounds__(256) scan_pass2_kernel(int dir,
                                                         const float* __restrict__ Alog,
                                                         const float* __restrict__ Dp) {
    int idx = blockIdx.x * 256 + threadIdx.x;   // 32768: (g,d,chunk)
    int ck = idx & (NCHUNK - 1);
    int d  = (idx >> 4) & (NC - 1);
    int g  = idx >> 12;
    float A[NST];
    #pragma unroll
    for (int n = 0; n < NST; n++) A[n] = -__expf(Alog[d * NST + n]);
    float Dd = Dp[d];
    size_t base = ((size_t)(dir * NG + g) * NC + d) * NL + ck * CHUNK;
    const float* dp = g_delta + base;
    const float* up = g_xc + base;
    const float* Bp = g_xdbl + ((size_t)(dir * NG + g) * NEDBL + NRK) * NL + ck * CHUNK;
    const float* Cp = g_xdbl + ((size_t)(dir * NG + g) * NEDBL + NRK + NST) * NL + ck * CHUNK;
    size_t co = (((size_t)(dir * NG + g) * NC + d) * NCHUNK + ck) * NST;
    float h[NST];
    #pragma unroll
    for (int n = 0; n < NST; n++) h[n] = g_hin[co + n];
    const float* zrow = g_z + ((size_t)(g * NC + d)) * NL;
    float*       yrow = g_y + ((size_t)(g * NC + d)) * NL;
    for (int t = 0; t < CHUNK; t++) {
        int l = ck * CHUNK + t;
        float dl = dp[t], ul = up[t];
        float du = dl * ul;
        float accv = 0.0f;
        #pragma unroll
        for (int n = 0; n < NST; n++) {
            float a = __expf(dl * A[n]);
            h[n] = fmaf(a, h[n], du * Bp[(size_t)n * NL + t]);
            accv = fmaf(h[n], Cp[(size_t)n * NL + t], accv);
        }
        float yv = fmaf(Dd, ul, accv);
        int lo = dir ? (NL - 1 - l) : l;
        float zv = zrow[lo];
        float gated = yv * (zv / (1.0f + __expf(-zv)));
        if (dir == 0) yrow[lo] = 0.5f * gated;
        else          yrow[lo] += 0.5f * gated;
    }
}

// ---------------------------------------------------------------------------
// 7. out_proj GEMM: g_gl[g,l,o] = sum_d g_y[g,d,l] * W[o,d]
//    A is [K=d][M=l] (l contiguous); C written o-contiguous.
// ---------------------------------------------------------------------------
__global__ void __launch_bounds__(256) gemm_out_kernel(const float* __restrict__ W) {
    __shared__ float As[16][132];
    __shared__ float Bs[16][68];
    const int l0 = blockIdx.x * 128;
    const int o0 = blockIdx.y * 64;
    const int g  = blockIdx.z;
    const int tid = threadIdx.x;
    const int tx = tid & 15, ty = tid >> 4;
    const int ob = tx * 4, lb = ty * 8;
    float acc[8][4];
    #pragma unroll
    for (int i = 0; i < 8; i++)
        #pragma unroll
        for (int j = 0; j < 4; j++) acc[i][j] = 0.0f;
    const float* A = g_y + (size_t)g * NC * NL;
    for (int k0 = 0; k0 < NC; k0 += 16) {
        #pragma unroll
        for (int it = 0; it < 2; it++) {
            int t = tid + it * 256;
            int row = t >> 5, lq = t & 31;
            float4 v = *reinterpret_cast<const float4*>(A + (size_t)(k0 + row) * NL + l0 + lq * 4);
            *reinterpret_cast<float4*>(&As[row][lq * 4]) = v;
        }
        {
            int row = tid >> 2, cq = tid & 3;
            float4 v = *reinterpret_cast<const float4*>(W + (size_t)(o0 + row) * NC + k0 + cq * 4);
            Bs[cq * 4 + 0][row] = v.x; Bs[cq * 4 + 1][row] = v.y;
            Bs[cq * 4 + 2][row] = v.z; Bs[cq * 4 + 3][row] = v.w;
        }
        __syncthreads();
        #pragma unroll
        for (int k = 0; k < 16; k++) {
            float4 a0 = *reinterpret_cast<const float4*>(&As[k][lb]);
            float4 a1 = *reinterpret_cast<const float4*>(&As[k][lb + 4]);
            float4 bq = *reinterpret_cast<const float4*>(&Bs[k][ob]);
            float av[8] = {a0.x, a0.y, a0.z, a0.w, a1.x, a1.y, a1.z, a1.w};
            float bv[4] = {bq.x, bq.y, bq.z, bq.w};
            #pragma unroll
            for (int i = 0; i < 8; i++)
                #pragma unroll
                for (int j = 0; j < 4; j++)
                    acc[i][j] = fmaf(av[i], bv[j], acc[i][j]);
        }
        __syncthreads();
    }
    #pragma unroll
    for (int i = 0; i < 8; i++) {
        int l = l0 + lb + i;
        float4 v = {acc[i][0], acc[i][1], acc[i][2], acc[i][3]};
        *reinterpret_cast<float4*>(g_gl + ((size_t)g * NL + l) * NC + o0 + ob) = v;
    }
}

// ---------------------------------------------------------------------------
// 8. final transpose g_x (g,l,c) -> out (g,c,h,w)
// ---------------------------------------------------------------------------
__global__ void __launch_bounds__(256) out_transpose_kernel(float* __restrict__ out) {
    __shared__ float tile[32][33];
    int g  = blockIdx.z;
    int c0 = blockIdx.y * 32;
    int l0 = blockIdx.x * 32;
    int tx = threadIdx.x;
    for (int r = threadIdx.y; r < 32; r += 8)
        tile[r][tx] = g_x[((size_t)g * NL + (l0 + r)) * NC + c0 + tx];
    __syncthreads();
    for (int r = threadIdx.y; r < 32; r += 8)
        out[((size_t)g * NC + (c0 + r)) * NL + l0 + tx] = tile[tx][r];
}

// ---------------------------------------------------------------------------
// Launch
// ---------------------------------------------------------------------------
extern "C" void kernel_launch(void* const* d_in, const int* in_sizes, int n_in,
                              void* d_out, int out_size) {
    const float* data       = (const float*)d_in[0];
    const float* ln_w       = (const float*)d_in[1];
    const float* ln_b       = (const float*)d_in[2];
    const float* in_proj_w  = (const float*)d_in[3];
    const float* conv_w     = (const float*)d_in[4];
    const float* conv_b     = (const float*)d_in[5];
    const float* x_proj_w   = (const float*)d_in[6];
    const float* dt_proj_w  = (const float*)d_in[7];
    const float* dt_proj_b  = (const float*)d_in[8];
    const float* A_log      = (const float*)d_in[9];
    const float* A_b_log    = (const float*)d_in[10];
    const float* Dparam     = (const float*)d_in[11];
    const float* out_proj_w = (const float*)d_in[12];
    const float* mn_w       = (const float*)d_in[13];
    const float* mn_b       = (const float*)d_in[14];
    const int*   record_len = (const int*)d_in[15];
    float* out = (float*)d_out;

    mean_kernel<<<dim3(NL / 32, NC / 32, NG), dim3(32, 8)>>>(data, record_len);

    for (int i = 0; i < NDEPTH; i++) {
        ln1_kernel<<<NG * NL, 256>>>(ln_w + i * NC, ln_b + i * NC);
        gemm_in_kernel<<<dim3(NL / 128, 512 / 64, NG), 256>>>(in_proj_w + (size_t)i * 512 * NC);
        conv_silu_kernel<<<(2 * NG * NC * NL) / 256, 256>>>(conv_w + i * NC * 4, conv_b + i * NC);
        gemm_xproj_kernel<<<dim3(NL / 256, 2 * NG), 256>>>(x_proj_w + (size_t)i * NEDBL * NC);
        dtproj_kernel<<<dim3(NL / 256, 2 * NG), 256>>>(dt_proj_w + (size_t)i * NC * NRK,
                                                       dt_proj_b + i * NC);
        scan_pass1_kernel<<<(2 * NG * NC * NCHUNK) / 256, 256>>>(A_log + (size_t)i * NC * NST,
                                                                 A_b_log + (size_t)i * NC * NST);
        scan_combine_kernel<<<(2 * NG * NC * NST) / 256, 256>>>();
        scan_pass2_kernel<<<(NG * NC * NCHUNK) / 256, 256>>>(0, A_log + (size_t)i * NC * NST,
                                                             Dparam + i * NC);
        scan_pass2_kernel<<<(NG * NC * NCHUNK) / 256, 256>>>(1, A_b_log + (size_t)i * NC * NST,
                                                             Dparam + i * NC);
        gemm_out_kernel<<<dim3(NL / 128, NC / 64, NG), 256>>>(out_proj_w + (size_t)i * NC * NC);
        ln2_kernel<<<NG * NL, 256>>>(mn_w + i * NC, mn_b + i * NC);
    }

    out_transpose_kernel<<<dim3(NL / 32, NC / 32, NG), dim3(32, 8)>>>(out);
}

// round 2
// speedup vs baseline: 2.4626x; 2.4626x over previous
#include <cuda_runtime.h>
#include <math.h>

// ---------------------------------------------------------------------------
// Problem constants
// ---------------------------------------------------------------------------
#define NG     8       // groups
#define NC     256     // channels (DIM)
#define NL     4096    // sequence length (64*64)
#define NST    8       // D_STATE
#define NRK    16      // DT_RANK
#define NEDBL  32      // DT_RANK + 2*D_STATE
#define NCHUNK 32
#define CHUNK  128     // NL / NCHUNK
#define NDEPTH 4

// ---------------------------------------------------------------------------
// Scratch (device globals) — all activation tensors are (l, d)-major now.
// ---------------------------------------------------------------------------
__device__ float g_x   [NG * NL * NC];            // (g, l, c) residual stream
__device__ float g_xn  [NG * NL * NC];            // (g, l, c) layernormed
__device__ float g_xz  [NG * NL * 2 * NC];        // (g, l, e) in_proj out: [xx|z]
__device__ float g_xc  [2 * NG * NL * NC];        // (dir, g, l, d) conv+silu
__device__ float g_xdbl[2 * NG * NL * NEDBL];     // (dir, g, l, e) dt|B|C
__device__ float g_y   [NG * NL * NC];            // (g, l, d) merged scan output
__device__ float g_gl  [NG * NL * NC];            // (g, l, o) out_proj output
__device__ float g_ap  [2 * NG * NCHUNK * NST * NC];
__device__ float g_hend[2 * NG * NCHUNK * NST * NC];
__device__ float g_hin [2 * NG * NCHUNK * NST * NC];

// ---------------------------------------------------------------------------
// 1. Segment mean + transpose (G*A, C, L) -> g_x (g, l, c)
// ---------------------------------------------------------------------------
__global__ void __launch_bounds__(256) mean_kernel(const float* __restrict__ data,
                                                   const int* __restrict__ rl) {
    __shared__ float tile[32][33];
    int g  = blockIdx.z;
    int c0 = blockIdx.y * 32;
    int l0 = blockIdx.x * 32;
    int start = 0;
    for (int gg = 0; gg < g; gg++) start += rl[gg];
    int cnt = rl[g];
    float inv = 1.0f / (float)cnt;
    int tx = threadIdx.x;
    for (int r = threadIdx.y; r < 32; r += 8) {
        float s = 0.0f;
        for (int a = 0; a < cnt; a++)
            s += data[((size_t)(start + a) * NC + (c0 + r)) * NL + l0 + tx];
        tile[r][tx] = s * inv;
    }
    __syncthreads();
    for (int r = threadIdx.y; r < 32; r += 8)
        g_x[((size_t)g * NL + (l0 + r)) * NC + c0 + tx] = tile[tx][r];
}

// ---------------------------------------------------------------------------
// LayerNorm: one warp per row, 8 channels per lane (2x float4), shuffle reduce
// ---------------------------------------------------------------------------
__device__ __forceinline__ void warp_ln(const float4 v0, const float4 v1,
                                        float& mu, float& rstd) {
    float s  = v0.x + v0.y + v0.z + v0.w + v1.x + v1.y + v1.z + v1.w;
    float s2 = v0.x*v0.x + v0.y*v0.y + v0.z*v0.z + v0.w*v0.w
             + v1.x*v1.x + v1.y*v1.y + v1.z*v1.z + v1.w*v1.w;
    #pragma unroll
    for (int off = 16; off; off >>= 1) {
        s  += __shfl_xor_sync(0xffffffffu, s, off);
        s2 += __shfl_xor_sync(0xffffffffu, s2, off);
    }
    mu = s * (1.0f / NC);
    float var = s2 * (1.0f / NC) - mu * mu;
    rstd = rsqrtf(var + 1e-5f);
}

__global__ void __launch_bounds__(256) ln1_kernel(const float* __restrict__ w,
                                                  const float* __restrict__ b) {
    int row  = blockIdx.x * 8 + (threadIdx.x >> 5);
    int lane = threadIdx.x & 31;
    const float* xr = g_x + (size_t)row * NC + lane * 8;
    float4 v0 = *(const float4*)(xr);
    float4 v1 = *(const float4*)(xr + 4);
    float mu, rstd;
    warp_ln(v0, v1, mu, rstd);
    float4 w0 = *(const float4*)(w + lane * 8);
    float4 w1 = *(const float4*)(w + lane * 8 + 4);
    float4 b0 = *(const float4*)(b + lane * 8);
    float4 b1 = *(const float4*)(b + lane * 8 + 4);
    float4 o0, o1;
    o0.x = (v0.x - mu) * rstd * w0.x + b0.x;  o0.y = (v0.y - mu) * rstd * w0.y + b0.y;
    o0.z = (v0.z - mu) * rstd * w0.z + b0.z;  o0.w = (v0.w - mu) * rstd * w0.w + b0.w;
    o1.x = (v1.x - mu) * rstd * w1.x + b1.x;  o1.y = (v1.y - mu) * rstd * w1.y + b1.y;
    o1.z = (v1.z - mu) * rstd * w1.z + b1.z;  o1.w = (v1.w - mu) * rstd * w1.w + b1.w;
    float* orow = g_xn + (size_t)row * NC + lane * 8;
    *(float4*)(orow)     = o0;
    *(float4*)(orow + 4) = o1;
}

__global__ void __launch_bounds__(256) ln2_kernel(const float* __restrict__ w,
                                                  const float* __restrict__ b) {
    int row  = blockIdx.x * 8 + (threadIdx.x >> 5);
    int lane = threadIdx.x & 31;
    const float* xr = g_gl + (size_t)row * NC + lane * 8;
    float4 v0 = *(const float4*)(xr);
    float4 v1 = *(const float4*)(xr + 4);
    float mu, rstd;
    warp_ln(v0, v1, mu, rstd);
    float4 w0 = *(const float4*)(w + lane * 8);
    float4 w1 = *(const float4*)(w + lane * 8 + 4);
    float4 b0 = *(const float4*)(b + lane * 8);
    float4 b1 = *(const float4*)(b + lane * 8 + 4);
    float* srow = g_x + (size_t)row * NC + lane * 8;
    float4 s0 = *(const float4*)(srow);
    float4 s1 = *(const float4*)(srow + 4);
    float4 o0, o1;
    o0.x = (v0.x - mu) * rstd * w0.x + b0.x + s0.x;  o0.y = (v0.y - mu) * rstd * w0.y + b0.y + s0.y;
    o0.z = (v0.z - mu) * rstd * w0.z + b0.z + s0.z;  o0.w = (v0.w - mu) * rstd * w0.w + b0.w + s0.w;
    o1.x = (v1.x - mu) * rstd * w1.x + b1.x + s1.x;  o1.y = (v1.y - mu) * rstd * w1.y + b1.y + s1.y;
    o1.z = (v1.z - mu) * rstd * w1.z + b1.z + s1.z;  o1.w = (v1.w - mu) * rstd * w1.w + b1.w + s1.w;
    *(float4*)(srow)     = o0;
    *(float4*)(srow + 4) = o1;
}

// ---------------------------------------------------------------------------
// 2. Unified fp32 GEMM: C[g][m][n] = sum_k A[g][m][k] * W[n][k]
//    A row-major (stride 256), W row-major (stride 256), C row-major (ldc).
//    BM=BN=128, BK=16; 256 threads, 8x8 per thread.
// ---------------------------------------------------------------------------
__global__ void __launch_bounds__(256) gemm128_kernel(const float* __restrict__ A,
                                                      const float* __restrict__ W,
                                                      float* __restrict__ C, int ldc) {
    __shared__ float As[16][132];
    __shared__ float Bs[16][132];
    const int l0 = blockIdx.x * 128;
    const int n0 = blockIdx.y * 128;
    const int g  = blockIdx.z;
    const int tid = threadIdx.x;
    const int tx = tid & 15, ty = tid >> 4;
    const float* Ag = A + (size_t)g * NL * NC;
    float* Cg = C + (size_t)g * NL * ldc;
    float acc[8][8];
    #pragma unroll
    for (int i = 0; i < 8; i++)
        #pragma unroll
        for (int j = 0; j < 8; j++) acc[i][j] = 0.0f;
    for (int k0 = 0; k0 < NC; k0 += 16) {
        #pragma unroll
        for (int it = 0; it < 2; it++) {
            int t = tid + it * 256;
            int row = t >> 2, cq = t & 3;
            float4 v = *reinterpret_cast<const float4*>(Ag + (size_t)(l0 + row) * NC + k0 + cq * 4);
            As[cq * 4 + 0][row] = v.x; As[cq * 4 + 1][row] = v.y;
            As[cq * 4 + 2][row] = v.z; As[cq * 4 + 3][row] = v.w;
            float4 u = *reinterpret_cast<const float4*>(W + (size_t)(n0 + row) * NC + k0 + cq * 4);
            Bs[cq * 4 + 0][row] = u.x; Bs[cq * 4 + 1][row] = u.y;
            Bs[cq * 4 + 2][row] = u.z; Bs[cq * 4 + 3][row] = u.w;
        }
        __syncthreads();
        #pragma unroll
        for (int k = 0; k < 16; k++) {
            float4 a0 = *reinterpret_cast<const float4*>(&As[k][ty * 8]);
            float4 a1 = *reinterpret_cast<const float4*>(&As[k][ty * 8 + 4]);
            float4 b0 = *reinterpret_cast<const float4*>(&Bs[k][tx * 8]);
            float4 b1 = *reinterpret_cast<const float4*>(&Bs[k][tx * 8 + 4]);
            float av[8] = {a0.x, a0.y, a0.z, a0.w, a1.x, a1.y, a1.z, a1.w};
            float bv[8] = {b0.x, b0.y, b0.z, b0.w, b1.x, b1.y, b1.z, b1.w};
            #pragma unroll
            for (int i = 0; i < 8; i++)
                #pragma unroll
                for (int j = 0; j < 8; j++)
                    acc[i][j] = fmaf(av[i], bv[j], acc[i][j]);
        }
        __syncthreads();
    }
    #pragma unroll
    for (int i = 0; i < 8; i++) {
        int row = l0 + ty * 8 + i;
        float4 v0 = {acc[i][0], acc[i][1], acc[i][2], acc[i][3]};
        float4 v1 = {acc[i][4], acc[i][5], acc[i][6], acc[i][7]};
        *reinterpret_cast<float4*>(Cg + (size_t)row * ldc + n0 + tx * 8)     = v0;
        *reinterpret_cast<float4*>(Cg + (size_t)row * ldc + n0 + tx * 8 + 4) = v1;
    }
}

// ---------------------------------------------------------------------------
// 3. causal depthwise conv (k=4) + SiLU, (l,d)-major, 8 l per thread
// ---------------------------------------------------------------------------
__global__ void __launch_bounds__(256) conv_silu_kernel(const float* __restrict__ cw,
                                                        const float* __restrict__ cb) {
    int d  = threadIdx.x;
    int l0 = blockIdx.x * 8;
    int dg = blockIdx.y;
    int dir = dg >> 3, g = dg & 7;
    float4 wv = *reinterpret_cast<const float4*>(cw + d * 4);
    float bias = cb[d];
    const float* X = g_xz + (size_t)g * NL * (2 * NC) + d;   // xx part, stride 512
    // rolling window: x0 = x[l0-3], x1 = x[l0-2], x2 = x[l0-1] (scan-domain)
    float x0 = 0.f, x1 = 0.f, x2 = 0.f;
    {
        int lj;
        lj = l0 - 3; if (lj >= 0) x0 = X[(size_t)(dir ? (NL - 1 - lj) : lj) * (2 * NC)];
        lj = l0 - 2; if (lj >= 0) x1 = X[(size_t)(dir ? (NL - 1 - lj) : lj) * (2 * NC)];
        lj = l0 - 1; if (lj >= 0) x2 = X[(size_t)(dir ? (NL - 1 - lj) : lj) * (2 * NC)];
    }
    float* out = g_xc + ((size_t)dg * NL + l0) * NC + d;
    #pragma unroll
    for (int i = 0; i < 8; i++) {
        int l = l0 + i;
        int src = dir ? (NL - 1 - l) : l;
        float x3 = X[(size_t)src * (2 * NC)];
        float s = bias;
        s = fmaf(wv.x, x0, s); s = fmaf(wv.y, x1, s);
        s = fmaf(wv.z, x2, s); s = fmaf(wv.w, x3, s);
        out[(size_t)i * NC] = s / (1.0f + __expf(-s));
        x0 = x1; x1 = x2; x2 = x3;
    }
}

// ---------------------------------------------------------------------------
// 4. x_proj GEMM: xdbl[dg][l][e] = sum_d xc[dg][l][d] * W[e][d]
//    BM=256(l), BN=32(e), BK=16; 256 threads, 8l x 4e per thread.
// ---------------------------------------------------------------------------
__global__ void __launch_bounds__(256) gemm_xproj_kernel(const float* __restrict__ W) {
    __shared__ float As[16][260];
    __shared__ float Bs[16][36];
    const int l0 = blockIdx.x * 256;
    const int dg = blockIdx.y;
    const int tid = threadIdx.x;
    const int tx = tid & 31, ty = tid >> 5;
    const int lb = tx * 8, eb = ty * 4;
    const float* A = g_xc + (size_t)dg * NL * NC;
    float acc[4][8];
    #pragma unroll
    for (int j = 0; j < 4; j++)
        #pragma unroll
        for (int i = 0; i < 8; i++) acc[j][i] = 0.0f;
    for (int k0 = 0; k0 < NC; k0 += 16) {
        #pragma unroll
        for (int it = 0; it < 4; it++) {
            int t = tid + it * 256;
            int row = t >> 2, cq = t & 3;
            float4 v = *reinterpret_cast<const float4*>(A + (size_t)(l0 + row) * NC + k0 + cq * 4);
            As[cq * 4 + 0][row] = v.x; As[cq * 4 + 1][row] = v.y;
            As[cq * 4 + 2][row] = v.z; As[cq * 4 + 3][row] = v.w;
        }
        if (tid < 128) {
            int row = tid >> 2, cq = tid & 3;
            float4 v = *reinterpret_cast<const float4*>(W + (size_t)row * NC + k0 + cq * 4);
            Bs[cq * 4 + 0][row] = v.x; Bs[cq * 4 + 1][row] = v.y;
            Bs[cq * 4 + 2][row] = v.z; Bs[cq * 4 + 3][row] = v.w;
        }
        __syncthreads();
        #pragma unroll
        for (int k = 0; k < 16; k++) {
            float4 a0 = *reinterpret_cast<const float4*>(&As[k][lb]);
            float4 a1 = *reinterpret_cast<const float4*>(&As[k][lb + 4]);
            float4 bq = *reinterpret_cast<const float4*>(&Bs[k][eb]);
            float av[8] = {a0.x, a0.y, a0.z, a0.w, a1.x, a1.y, a1.z, a1.w};
            float bv[4] = {bq.x, bq.y, bq.z, bq.w};
            #pragma unroll
            for (int j = 0; j < 4; j++)
                #pragma unroll
                for (int i = 0; i < 8; i++)
                    acc[j][i] = fmaf(av[i], bv[j], acc[j][i]);
        }
        __syncthreads();
    }
    float* O = g_xdbl + (size_t)dg * NL * NEDBL;
    #pragma unroll
    for (int i = 0; i < 8; i++) {
        int l = l0 + lb + i;
        float4 v = {acc[0][i], acc[1][i], acc[2][i], acc[3][i]};
        *reinterpret_cast<float4*>(O + (size_t)l * NEDBL + eb) = v;
    }
}

// ---------------------------------------------------------------------------
// 5+6. Fused scan: dt_proj + softplus + selective scan, (l,d)-major.
// ---------------------------------------------------------------------------
__device__ __forceinline__ float softplusf(float s) {
    return (s > 20.0f) ? s : log1pf(__expf(s));
}

// pass 1: per-chunk A-product and end-state
__global__ void __launch_bounds__(256) scan_pass1_kernel(const float* __restrict__ Wdt,
                                                         const float* __restrict__ dtb,
                                                         const float* __restrict__ AlogF,
                                                         const float* __restrict__ AlogB) {
    __shared__ float sm[CHUNK * 36];
    const int d  = threadIdx.x;
    const int ck = blockIdx.x;
    const int dg = blockIdx.y;
    const int dir = dg >> 3;
    // stage xdbl tile (CHUNK x 32) into shared, padded stride 36
    {
        const float* xd = g_xdbl + ((size_t)dg * NL + ck * CHUNK) * NEDBL;
        #pragma unroll
        for (int it = 0; it < 4; it++) {
            int flat = threadIdx.x + it * 256;   // 1024 float4
            int row = flat >> 3, c4 = flat & 7;
            float4 v = *reinterpret_cast<const float4*>(xd + (size_t)row * NEDBL + c4 * 4);
            *reinterpret_cast<float4*>(&sm[row * 36 + c4 * 4]) = v;
        }
    }
    __syncthreads();
    const float* Alog = (dir ? AlogB : AlogF) + d * NST;
    float A[NST];
    #pragma unroll
    for (int n = 0; n < NST; n++) A[n] = -__expf(Alog[n]);
    float Wr[NRK];
    #pragma unroll
    for (int q = 0; q < 4; q++) {
        float4 v = *reinterpret_cast<const float4*>(Wdt + d * NRK + q * 4);
        Wr[q * 4] = v.x; Wr[q * 4 + 1] = v.y; Wr[q * 4 + 2] = v.z; Wr[q * 4 + 3] = v.w;
    }
    float bias = dtb[d];
    const float* xcp = g_xc + ((size_t)dg * NL + ck * CHUNK) * NC + d;
    float h[NST], ap[NST];
    #pragma unroll
    for (int n = 0; n < NST; n++) { h[n] = 0.0f; ap[n] = 1.0f; }
    for (int t = 0; t < CHUNK; t++) {
        const float* srow = sm + t * 36;
        float s = bias;
        #pragma unroll
        for (int r = 0; r < NRK; r++) s = fmaf(Wr[r], srow[r], s);
        float dl = softplusf(s);
        float u = xcp[(size_t)t * NC];
        float du = dl * u;
        #pragma unroll
        for (int n = 0; n < NST; n++) {
            float a = __expf(dl * A[n]);
            ap[n] *= a;
            h[n] = fmaf(a, h[n], du * srow[NRK + n]);
        }
    }
    float* apO = g_ap   + (((size_t)dg * NCHUNK + ck) * NST) * NC + d;
    float* heO = g_hend + (((size_t)dg * NCHUNK + ck) * NST) * NC + d;
    #pragma unroll
    for (int n = 0; n < NST; n++) { apO[n * NC] = ap[n]; heO[n * NC] = h[n]; }
}

// sequential chunk combine
__global__ void __launch_bounds__(256) scan_combine_kernel() {
    int idx = blockIdx.x * 256 + threadIdx.x;   // 32768: (dg, n, d), d fastest
    int d  = idx & (NC - 1);
    int n  = (idx >> 8) & 7;
    int dg = idx >> 11;
    size_t base = ((size_t)dg * NCHUNK * NST + n) * NC + d;
    float h = 0.0f;
    for (int k = 0; k < NCHUNK; k++) {
        size_t o = base + (size_t)k * NST * NC;
        g_hin[o] = h;
        h = g_ap[o] * h + g_hend[o];
    }
}

// pass 2: replay with carry-in; emit gated output (dir0 writes, dir1 adds)
__global__ void __launch_bounds__(256) scan_pass2_kernel(int dir,
                                                         const float* __restrict__ Wdt,
                                                         const float* __restrict__ dtb,
                                                         const float* __restrict__ Alog,
                                                         const float* __restrict__ Dp) {
    __shared__ float sm[CHUNK * 36];
    const int d  = threadIdx.x;
    const int ck = blockIdx.x;
    const int g  = blockIdx.y;
    const int dg = dir * NG + g;
    {
        const float* xd = g_xdbl + ((size_t)dg * NL + ck * CHUNK) * NEDBL;
        #pragma unroll
        for (int it = 0; it < 4; it++) {
            int flat = threadIdx.x + it * 256;
            int row = flat >> 3, c4 = flat & 7;
            float4 v = *reinterpret_cast<const float4*>(xd + (size_t)row * NEDBL + c4 * 4);
            *reinterpret_cast<float4*>(&sm[row * 36 + c4 * 4]) = v;
        }
    }
    __syncthreads();
    float A[NST];
    #pragma unroll
    for (int n = 0; n < NST; n++) A[n] = -__expf(Alog[d * NST + n]);
    float Wr[NRK];
    #pragma unroll
    for (int q = 0; q < 4; q++) {
        float4 v = *reinterpret_cast<const float4*>(Wdt + d * NRK + q * 4);
        Wr[q * 4] = v.x; Wr[q * 4 + 1] = v.y; Wr[q * 4 + 2] = v.z; Wr[q * 4 + 3] = v.w;
    }
    float bias = dtb[d];
    float Dd = Dp[d];
    const float* xcp = g_xc + ((size_t)dg * NL + ck * CHUNK) * NC + d;
    const float* hiP = g_hin + (((size_t)dg * NCHUNK + ck) * NST) * NC + d;
    float h[NST];
    #pragma unroll
    for (int n = 0; n < NST; n++) h[n] = hiP[n * NC];
    for (int t = 0; t < CHUNK; t++) {
        const float* srow = sm + t * 36;
        float s = bias;
        #pragma unroll
        for (int r = 0; r < NRK; r++) s = fmaf(Wr[r], srow[r], s);
        float dl = softplusf(s);
        float u = xcp[(size_t)t * NC];
        float du = dl * u;
        float accv = 0.0f;
        #pragma unroll
        for (int n = 0; n < NST; n++) {
            float a = __expf(dl * A[n]);
            h[n] = fmaf(a, h[n], du * srow[NRK + n]);
            accv = fmaf(h[n], srow[NRK + NST + n], accv);
        }
        float yv = fmaf(Dd, u, accv);
        int l  = ck * CHUNK + t;
        int lo = dir ? (NL - 1 - l) : l;
        float zv = g_xz[((size_t)g * NL + lo) * (2 * NC) + NC + d];
        float gated = 0.5f * yv * (zv / (1.0f + __expf(-zv)));
        float* yp = g_y + ((size_t)g * NL + lo) * NC + d;
        if (dir == 0) *yp = gated;
        else          *yp += gated;
    }
}

// ---------------------------------------------------------------------------
// 8. final transpose g_x (g,l,c) -> out (g,c,h,w)
// ---------------------------------------------------------------------------
__global__ void __launch_bounds__(256) out_transpose_kernel(float* __restrict__ out) {
    __shared__ float tile[32][33];
    int g  = blockIdx.z;
    int c0 = blockIdx.y * 32;
    int l0 = blockIdx.x * 32;
    int tx = threadIdx.x;
    for (int r = threadIdx.y; r < 32; r += 8)
        tile[r][tx] = g_x[((size_t)g * NL + (l0 + r)) * NC + c0 + tx];
    __syncthreads();
    for (int r = threadIdx.y; r < 32; r += 8)
        out[((size_t)g * NC + (c0 + r)) * NL + l0 + tx] = tile[tx][r];
}

// ---------------------------------------------------------------------------
// Launch
// ---------------------------------------------------------------------------
extern "C" void kernel_launch(void* const* d_in, const int* in_sizes, int n_in,
                              void* d_out, int out_size) {
    const float* data       = (const float*)d_in[0];
    const float* ln_w       = (const float*)d_in[1];
    const float* ln_b       = (const float*)d_in[2];
    const float* in_proj_w  = (const float*)d_in[3];
    const float* conv_w     = (const float*)d_in[4];
    const float* conv_b     = (const float*)d_in[5];
    const float* x_proj_w   = (const float*)d_in[6];
    const float* dt_proj_w  = (const float*)d_in[7];
    const float* dt_proj_b  = (const float*)d_in[8];
    const float* A_log      = (const float*)d_in[9];
    const float* A_b_log    = (const float*)d_in[10];
    const float* Dparam     = (const float*)d_in[11];
    const float* out_proj_w = (const float*)d_in[12];
    const float* mn_w       = (const float*)d_in[13];
    const float* mn_b       = (const float*)d_in[14];
    const int*   record_len = (const int*)d_in[15];
    float* out = (float*)d_out;

    float* d_xn; cudaGetSymbolAddress((void**)&d_xn, g_xn);
    float* d_xz; cudaGetSymbolAddress((void**)&d_xz, g_xz);
    float* d_y;  cudaGetSymbolAddress((void**)&d_y,  g_y);
    float* d_gl; cudaGetSymbolAddress((void**)&d_gl, g_gl);

    mean_kernel<<<dim3(NL / 32, NC / 32, NG), dim3(32, 8)>>>(data, record_len);

    for (int i = 0; i < NDEPTH; i++) {
        ln1_kernel<<<NG * NL / 8, 256>>>(ln_w + i * NC, ln_b + i * NC);
        gemm128_kernel<<<dim3(NL / 128, 512 / 128, NG), 256>>>(
            d_xn, in_proj_w + (size_t)i * 512 * NC, d_xz, 512);
        conv_silu_kernel<<<dim3(NL / 8, 2 * NG), 256>>>(conv_w + i * NC * 4, conv_b + i * NC);
        gemm_xproj_kernel<<<dim3(NL / 256, 2 * NG), 256>>>(x_proj_w + (size_t)i * NEDBL * NC);
        scan_pass1_kernel<<<dim3(NCHUNK, 2 * NG), 256>>>(
            dt_proj_w + (size_t)i * NC * NRK, dt_proj_b + i * NC,
            A_log + (size_t)i * NC * NST, A_b_log + (size_t)i * NC * NST);
        scan_combine_kernel<<<(2 * NG * NST * NC) / 256, 256>>>();
        scan_pass2_kernel<<<dim3(NCHUNK, NG), 256>>>(0,
            dt_proj_w + (size_t)i * NC * NRK, dt_proj_b + i * NC,
            A_log + (size_t)i * NC * NST, Dparam + i * NC);
        scan_pass2_kernel<<<dim3(NCHUNK, NG), 256>>>(1,
            dt_proj_w + (size_t)i * NC * NRK, dt_proj_b + i * NC,
            A_b_log + (size_t)i * NC * NST, Dparam + i * NC);
        gemm128_kernel<<<dim3(NL / 128, NC / 128, NG), 256>>>(
            d_y, out_proj_w + (size_t)i * NC * NC, d_gl, 256);
        ln2_kernel<<<NG * NL / 8, 256>>>(mn_w + i * NC, mn_b + i * NC);
    }

    out_transpose_kernel<<<dim3(NL / 32, NC / 32, NG), dim3(32, 8)>>>(out);
}

// round 4
// speedup vs baseline: 3.0280x; 1.2296x over previous
#include <cuda_runtime.h>
#include <cuda_bf16.h>
#include <math.h>
#include <stdint.h>

// ---------------------------------------------------------------------------
// Problem constants
// ---------------------------------------------------------------------------
#define NG     8
#define NC     256
#define NL     4096
#define NST    8
#define NRK    16
#define NEDBL  32
#define NCHUNK 32
#define CHUNK  128
#define NDEPTH 4

// ---------------------------------------------------------------------------
// Scratch
// ---------------------------------------------------------------------------
__device__ float g_x   [NG * NL * NC];
__device__ float g_xz  [NG * NL * 2 * NC];
__device__ float g_xc  [2 * NG * NL * NC];
__device__ float g_xdbl[2 * NG * NL * NEDBL];
__device__ float g_y   [NG * NL * NC];
__device__ float g_gl  [NG * NL * NC];
__device__ float g_ap  [2 * NG * NCHUNK * NST * NC];
__device__ float g_hend[2 * NG * NCHUNK * NST * NC];
__device__ float g_hin [2 * NG * NCHUNK * NST * NC];
__device__ __nv_bfloat16 g_xnh[NG * NL * NC];
__device__ __nv_bfloat16 g_xnl[NG * NL * NC];
__device__ __nv_bfloat16 g_wih[NDEPTH * 512 * NC], g_wil[NDEPTH * 512 * NC];
__device__ __nv_bfloat16 g_wxh[NDEPTH * NEDBL * NC], g_wxl[NDEPTH * NEDBL * NC];
__device__ __nv_bfloat16 g_woh[NDEPTH * NC * NC], g_wol[NDEPTH * NC * NC];

// ---------------------------------------------------------------------------
// Small helpers
// ---------------------------------------------------------------------------
__device__ __forceinline__ uint32_t smem_u32(const void* p) {
    uint32_t a;
    asm("{ .reg .u64 t; cvta.to.shared.u64 t, %1; cvt.u32.u64 %0, t; }" : "=r"(a) : "l"(p));
    return a;
}
__device__ __forceinline__ uint32_t pack2(__nv_bfloat16 a, __nv_bfloat16 b) {
    __nv_bfloat162 t(a, b);
    return *reinterpret_cast<uint32_t*>(&t);
}
__device__ __forceinline__ void bsplit(float v, __nv_bfloat16& h, __nv_bfloat16& l) {
    h = __float2bfloat16(v);
    l = __float2bfloat16(v - __bfloat162float(h));
}

__device__ __forceinline__ void ldsm_x4(uint32_t& r0, uint32_t& r1, uint32_t& r2,
                                        uint32_t& r3, uint32_t addr) {
    asm volatile("ldmatrix.sync.aligned.m8n8.x4.shared.b16 {%0,%1,%2,%3}, [%4];"
                 : "=r"(r0), "=r"(r1), "=r"(r2), "=r"(r3) : "r"(addr));
}
__device__ __forceinline__ void ldsm_x2(uint32_t& r0, uint32_t& r1, uint32_t addr) {
    asm volatile("ldmatrix.sync.aligned.m8n8.x2.shared.b16 {%0,%1}, [%2];"
                 : "=r"(r0), "=r"(r1) : "r"(addr));
}
__device__ __forceinline__ void mma_bf16(float* d, const uint32_t* a, const uint32_t* b) {
    asm volatile("mma.sync.aligned.m16n8k16.row.col.f32.bf16.bf16.f32 "
                 "{%0,%1,%2,%3}, {%4,%5,%6,%7}, {%8,%9}, {%0,%1,%2,%3};"
                 : "+f"(d[0]), "+f"(d[1]), "+f"(d[2]), "+f"(d[3])
                 : "r"(a[0]), "r"(a[1]), "r"(a[2]), "r"(a[3]), "r"(b[0]), "r"(b[1]));
}

// ---------------------------------------------------------------------------
// Weight split kernel (fp32 -> bf16 hi/lo)
// ---------------------------------------------------------------------------
__global__ void __launch_bounds__(256) wsplit_kernel(const float* __restrict__ w,
                                                     __nv_bfloat16* __restrict__ h,
                                                     __nv_bfloat16* __restrict__ l, int n) {
    int i = blockIdx.x * 256 + threadIdx.x;
    if (i < n) {
        __nv_bfloat16 hh, ll;
        bsplit(w[i], hh, ll);
        h[i] = hh; l[i] = ll;
    }
}

// ---------------------------------------------------------------------------
// 1. Segment mean + transpose
// ---------------------------------------------------------------------------
__global__ void __launch_bounds__(256) mean_kernel(const float* __restrict__ data,
                                                   const int* __restrict__ rl) {
    __shared__ float tile[32][33];
    int g  = blockIdx.z;
    int c0 = blockIdx.y * 32;
    int l0 = blockIdx.x * 32;
    int start = 0;
    for (int gg = 0; gg < g; gg++) start += rl[gg];
    int cnt = rl[g];
    float inv = 1.0f / (float)cnt;
    int tx = threadIdx.x;
    for (int r = threadIdx.y; r < 32; r += 8) {
        float s = 0.0f;
        for (int a = 0; a < cnt; a++)
            s += data[((size_t)(start + a) * NC + (c0 + r)) * NL + l0 + tx];
        tile[r][tx] = s * inv;
    }
    __syncthreads();
    for (int r = threadIdx.y; r < 32; r += 8)
        g_x[((size_t)g * NL + (l0 + r)) * NC + c0 + tx] = tile[tx][r];
}

// ---------------------------------------------------------------------------
// LayerNorm
// ---------------------------------------------------------------------------
__device__ __forceinline__ void warp_ln(const float4 v0, const float4 v1,
                                        float& mu, float& rstd) {
    float s  = v0.x + v0.y + v0.z + v0.w + v1.x + v1.y + v1.z + v1.w;
    float s2 = v0.x*v0.x + v0.y*v0.y + v0.z*v0.z + v0.w*v0.w
             + v1.x*v1.x + v1.y*v1.y + v1.z*v1.z + v1.w*v1.w;
    #pragma unroll
    for (int off = 16; off; off >>= 1) {
        s  += __shfl_xor_sync(0xffffffffu, s, off);
        s2 += __shfl_xor_sync(0xffffffffu, s2, off);
    }
    mu = s * (1.0f / NC);
    float var = s2 * (1.0f / NC) - mu * mu;
    rstd = rsqrtf(var + 1e-5f);
}

// LN1: g_x -> bf16 hi/lo split
__global__ void __launch_bounds__(256) ln1_kernel(const float* __restrict__ w,
                                                  const float* __restrict__ b) {
    int row  = blockIdx.x * 8 + (threadIdx.x >> 5);
    int lane = threadIdx.x & 31;
    const float* xr = g_x + (size_t)row * NC + lane * 8;
    float4 v0 = *(const float4*)(xr);
    float4 v1 = *(const float4*)(xr + 4);
    float mu, rstd;
    warp_ln(v0, v1, mu, rstd);
    float4 w0 = *(const float4*)(w + lane * 8);
    float4 w1 = *(const float4*)(w + lane * 8 + 4);
    float4 b0 = *(const float4*)(b + lane * 8);
    float4 b1 = *(const float4*)(b + lane * 8 + 4);
    float o[8];
    o[0] = (v0.x - mu) * rstd * w0.x + b0.x;  o[1] = (v0.y - mu) * rstd * w0.y + b0.y;
    o[2] = (v0.z - mu) * rstd * w0.z + b0.z;  o[3] = (v0.w - mu) * rstd * w0.w + b0.w;
    o[4] = (v1.x - mu) * rstd * w1.x + b1.x;  o[5] = (v1.y - mu) * rstd * w1.y + b1.y;
    o[6] = (v1.z - mu) * rstd * w1.z + b1.z;  o[7] = (v1.w - mu) * rstd * w1.w + b1.w;
    __nv_bfloat16 hh[8], ll[8];
    #pragma unroll
    for (int i = 0; i < 8; i++) bsplit(o[i], hh[i], ll[i]);
    uint4 vh = {pack2(hh[0],hh[1]), pack2(hh[2],hh[3]), pack2(hh[4],hh[5]), pack2(hh[6],hh[7])};
    uint4 vl = {pack2(ll[0],ll[1]), pack2(ll[2],ll[3]), pack2(ll[4],ll[5]), pack2(ll[6],ll[7])};
    *reinterpret_cast<uint4*>(g_xnh + (size_t)row * NC + lane * 8) = vh;
    *reinterpret_cast<uint4*>(g_xnl + (size_t)row * NC + lane * 8) = vl;
}

// LN2 + residual -> g_x
__global__ void __launch_bounds__(256) ln2_kernel(const float* __restrict__ w,
                                                  const float* __restrict__ b) {
    int row  = blockIdx.x * 8 + (threadIdx.x >> 5);
    int lane = threadIdx.x & 31;
    const float* xr = g_gl + (size_t)row * NC + lane * 8;
    float4 v0 = *(const float4*)(xr);
    float4 v1 = *(const float4*)(xr + 4);
    float mu, rstd;
    warp_ln(v0, v1, mu, rstd);
    float4 w0 = *(const float4*)(w + lane * 8);
    float4 w1 = *(const float4*)(w + lane * 8 + 4);
    float4 b0 = *(const float4*)(b + lane * 8);
    float4 b1 = *(const float4*)(b + lane * 8 + 4);
    float* srow = g_x + (size_t)row * NC + lane * 8;
    float4 s0 = *(const float4*)(srow);
    float4 s1 = *(const float4*)(srow + 4);
    float4 o0, o1;
    o0.x = (v0.x - mu) * rstd * w0.x + b0.x + s0.x;  o0.y = (v0.y - mu) * rstd * w0.y + b0.y + s0.y;
    o0.z = (v0.z - mu) * rstd * w0.z + b0.z + s0.z;  o0.w = (v0.w - mu) * rstd * w0.w + b0.w + s0.w;
    o1.x = (v1.x - mu) * rstd * w1.x + b1.x + s1.x;  o1.y = (v1.y - mu) * rstd * w1.y + b1.y + s1.y;
    o1.z = (v1.z - mu) * rstd * w1.z + b1.z + s1.z;  o1.w = (v1.w - mu) * rstd * w1.w + b1.w + s1.w;
    *(float4*)(srow)     = o0;
    *(float4*)(srow + 4) = o1;
}

// ---------------------------------------------------------------------------
// HMMA GEMM: C[gz][m][n] = sum_k A[gz][m][k] * W[n][k]
//   bf16 hi/lo split (3 mma products), fp32 accumulate.
//   Block: 256 thr / 8 warps; tile M=128 x NT; warp tile 64 x WN.
//   SMEM rows padded to 40 bf16 (80 B): conflict-free ldmatrix.
// ---------------------------------------------------------------------------
template<int NT, bool AFP32>
__global__ void __launch_bounds__(256) gemm_mma(const void* __restrict__ Ap,
                                                const void* __restrict__ Alp,
                                                const __nv_bfloat16* __restrict__ Wh,
                                                const __nv_bfloat16* __restrict__ Wl,
                                                float* __restrict__ C, int ldc) {
    constexpr int WN   = (NT == 128) ? 32 : 8;
    constexpr int NSUB = WN / 8;
    __shared__ __nv_bfloat16 Ah_s[128][40];
    __shared__ __nv_bfloat16 Al_s[128][40];
    __shared__ __nv_bfloat16 Bh_s[NT][40];
    __shared__ __nv_bfloat16 Bl_s[NT][40];

    const int tid = threadIdx.x, wid = tid >> 5, lane = tid & 31;
    const int l0 = blockIdx.x * 128, n0 = blockIdx.y * NT, gz = blockIdx.z;
    const int wm = (wid & 1) * 64;
    const int wn = (wid >> 1) * WN;

    float acc[4][NSUB][4];
    #pragma unroll
    for (int mi = 0; mi < 4; mi++)
        #pragma unroll
        for (int ni = 0; ni < NSUB; ni++)
            #pragma unroll
            for (int q = 0; q < 4; q++) acc[mi][ni][q] = 0.0f;

    const int arow = tid >> 1, ahalf = tid & 1;

    for (int kc = 0; kc < NC; kc += 32) {
        // ---- stage A (128 x 32) ----
        if (!AFP32) {
            const __nv_bfloat16* Ahg = (const __nv_bfloat16*)Ap
                + (size_t)gz * NL * NC + (size_t)(l0 + arow) * NC + kc + ahalf * 16;
            const __nv_bfloat16* Alg = (const __nv_bfloat16*)Alp
                + (size_t)gz * NL * NC + (size_t)(l0 + arow) * NC + kc + ahalf * 16;
            uint4 h0 = *reinterpret_cast<const uint4*>(Ahg);
            uint4 h1 = *reinterpret_cast<const uint4*>(Ahg + 8);
            uint4 l0v = *reinterpret_cast<const uint4*>(Alg);
            uint4 l1v = *reinterpret_cast<const uint4*>(Alg + 8);
            *reinterpret_cast<uint4*>(&Ah_s[arow][ahalf * 16])     = h0;
            *reinterpret_cast<uint4*>(&Ah_s[arow][ahalf * 16 + 8]) = h1;
            *reinterpret_cast<uint4*>(&Al_s[arow][ahalf * 16])     = l0v;
            *reinterpret_cast<uint4*>(&Al_s[arow][ahalf * 16 + 8]) = l1v;
        } else {
            const float* Ag = (const float*)Ap
                + (size_t)gz * NL * NC + (size_t)(l0 + arow) * NC + kc + ahalf * 16;
            float f[16];
            #pragma unroll
            for (int q = 0; q < 4; q++)
                *reinterpret_cast<float4*>(&f[q * 4]) = *reinterpret_cast<const float4*>(Ag + q * 4);
            __nv_bfloat16 hh[16], ll[16];
            #pragma unroll
            for (int j = 0; j < 16; j++) bsplit(f[j], hh[j], ll[j]);
            uint4 vh0 = {pack2(hh[0],hh[1]),  pack2(hh[2],hh[3]),  pack2(hh[4],hh[5]),  pack2(hh[6],hh[7])};
            uint4 vh1 = {pack2(hh[8],hh[9]),  pack2(hh[10],hh[11]),pack2(hh[12],hh[13]),pack2(hh[14],hh[15])};
            uint4 vl0 = {pack2(ll[0],ll[1]),  pack2(ll[2],ll[3]),  pack2(ll[4],ll[5]),  pack2(ll[6],ll[7])};
            uint4 vl1 = {pack2(ll[8],ll[9]),  pack2(ll[10],ll[11]),pack2(ll[12],ll[13]),pack2(ll[14],ll[15])};
            *reinterpret_cast<uint4*>(&Ah_s[arow][ahalf * 16])     = vh0;
            *reinterpret_cast<uint4*>(&Ah_s[arow][ahalf * 16 + 8]) = vh1;
            *reinterpret_cast<uint4*>(&Al_s[arow][ahalf * 16])     = vl0;
            *reinterpret_cast<uint4*>(&Al_s[arow][ahalf * 16 + 8]) = vl1;
        }
        // ---- stage B (NT x 32) ----
        if (tid < NT * 2) {
            int brow = tid >> 1, bhalf = tid & 1;
            const __nv_bfloat16* Bhg = Wh + (size_t)(n0 + brow) * NC + kc + bhalf * 16;
            const __nv_bfloat16* Blg = Wl + (size_t)(n0 + brow) * NC + kc + bhalf * 16;
            uint4 h0 = *reinterpret_cast<const uint4*>(Bhg);
            uint4 h1 = *reinterpret_cast<const uint4*>(Bhg + 8);
            uint4 l0v = *reinterpret_cast<const uint4*>(Blg);
            uint4 l1v = *reinterpret_cast<const uint4*>(Blg + 8);
            *reinterpret_cast<uint4*>(&Bh_s[brow][bhalf * 16])     = h0;
            *reinterpret_cast<uint4*>(&Bh_s[brow][bhalf * 16 + 8]) = h1;
            *reinterpret_cast<uint4*>(&Bl_s[brow][bhalf * 16])     = l0v;
            *reinterpret_cast<uint4*>(&Bl_s[brow][bhalf * 16 + 8]) = l1v;
        }
        __syncthreads();
        #pragma unroll
        for (int kk = 0; kk < 32; kk += 16) {
            uint32_t ah[4][4], al[4][4];
            #pragma unroll
            for (int mi = 0; mi < 4; mi++) {
                uint32_t ad = smem_u32(&Ah_s[wm + mi * 16 + (lane & 15)][kk + (lane >> 4) * 8]);
                ldsm_x4(ah[mi][0], ah[mi][1], ah[mi][2], ah[mi][3], ad);
                ad = smem_u32(&Al_s[wm + mi * 16 + (lane & 15)][kk + (lane >> 4) * 8]);
                ldsm_x4(al[mi][0], al[mi][1], al[mi][2], al[mi][3], ad);
            }
            uint32_t bh[NSUB][2], bl[NSUB][2];
            #pragma unroll
            for (int ni = 0; ni < NSUB; ni++) {
                uint32_t bd = smem_u32(&Bh_s[wn + ni * 8 + (lane & 7)][kk + ((lane >> 3) & 1) * 8]);
                ldsm_x2(bh[ni][0], bh[ni][1], bd);
                bd = smem_u32(&Bl_s[wn + ni * 8 + (lane & 7)][kk + ((lane >> 3) & 1) * 8]);
                ldsm_x2(bl[ni][0], bl[ni][1], bd);
            }
            #pragma unroll
            for (int mi = 0; mi < 4; mi++)
                #pragma unroll
                for (int ni = 0; ni < NSUB; ni++) {
                    mma_bf16(acc[mi][ni], ah[mi], bh[ni]);
                    mma_bf16(acc[mi][ni], ah[mi], bl[ni]);
                    mma_bf16(acc[mi][ni], al[mi], bh[ni]);
                }
        }
        __syncthreads();
    }
    // ---- epilogue ----
    float* Cg = C + (size_t)gz * NL * ldc;
    #pragma unroll
    for (int mi = 0; mi < 4; mi++) {
        #pragma unroll
        for (int ni = 0; ni < NSUB; ni++) {
            int r = l0 + wm + mi * 16 + (lane >> 2);
            int c = n0 + wn + ni * 8 + (lane & 3) * 2;
            float2 v0 = {acc[mi][ni][0], acc[mi][ni][1]};
            float2 v1 = {acc[mi][ni][2], acc[mi][ni][3]};
            *reinterpret_cast<float2*>(Cg + (size_t)r * ldc + c)       = v0;
            *reinterpret_cast<float2*>(Cg + (size_t)(r + 8) * ldc + c) = v1;
        }
    }
}

// ---------------------------------------------------------------------------
// 3. causal depthwise conv (k=4) + SiLU
// ---------------------------------------------------------------------------
__global__ void __launch_bounds__(256) conv_silu_kernel(const float* __restrict__ cw,
                                                        const float* __restrict__ cb) {
    int d  = threadIdx.x;
    int l0 = blockIdx.x * 8;
    int dg = blockIdx.y;
    int dir = dg >> 3, g = dg & 7;
    float4 wv = *reinterpret_cast<const float4*>(cw + d * 4);
    float bias = cb[d];
    const float* X = g_xz + (size_t)g * NL * (2 * NC) + d;
    float x0 = 0.f, x1 = 0.f, x2 = 0.f;
    {
        int lj;
        lj = l0 - 3; if (lj >= 0) x0 = X[(size_t)(dir ? (NL - 1 - lj) : lj) * (2 * NC)];
        lj = l0 - 2; if (lj >= 0) x1 = X[(size_t)(dir ? (NL - 1 - lj) : lj) * (2 * NC)];
        lj = l0 - 1; if (lj >= 0) x2 = X[(size_t)(dir ? (NL - 1 - lj) : lj) * (2 * NC)];
    }
    float* out = g_xc + ((size_t)dg * NL + l0) * NC + d;
    #pragma unroll
    for (int i = 0; i < 8; i++) {
        int l = l0 + i;
        int src = dir ? (NL - 1 - l) : l;
        float x3 = X[(size_t)src * (2 * NC)];
        float s = bias;
        s = fmaf(wv.x, x0, s); s = fmaf(wv.y, x1, s);
        s = fmaf(wv.z, x2, s); s = fmaf(wv.w, x3, s);
        out[(size_t)i * NC] = s / (1.0f + __expf(-s));
        x0 = x1; x1 = x2; x2 = x3;
    }
}

// ---------------------------------------------------------------------------
// Fused scan (dt_proj + softplus + selective scan)
// ---------------------------------------------------------------------------
__device__ __forceinline__ float softplusf(float s) {
    return (s > 20.0f) ? s : log1pf(__expf(s));
}

__global__ void __launch_bounds__(256) scan_pass1_kernel(const float* __restrict__ Wdt,
                                                         const float* __restrict__ dtb,
                                                         const float* __restrict__ AlogF,
                                                         const float* __restrict__ AlogB) {
    __shared__ float sm[CHUNK * 36];
    const int d  = threadIdx.x;
    const int ck = blockIdx.x;
    const int dg = blockIdx.y;
    const int dir = dg >> 3;
    {
        const float* xd = g_xdbl + ((size_t)dg * NL + ck * CHUNK) * NEDBL;
        #pragma unroll
        for (int it = 0; it < 4; it++) {
            int flat = threadIdx.x + it * 256;
            int row = flat >> 3, c4 = flat & 7;
            float4 v = *reinterpret_cast<const float4*>(xd + (size_t)row * NEDBL + c4 * 4);
            *reinterpret_cast<float4*>(&sm[row * 36 + c4 * 4]) = v;
        }
    }
    __syncthreads();
    const float* Alog = (dir ? AlogB : AlogF) + d * NST;
    float A[NST];
    #pragma unroll
    for (int n = 0; n < NST; n++) A[n] = -__expf(Alog[n]);
    float Wr[NRK];
    #pragma unroll
    for (int q = 0; q < 4; q++) {
        float4 v = *reinterpret_cast<const float4*>(Wdt + d * NRK + q * 4);
        Wr[q * 4] = v.x; Wr[q * 4 + 1] = v.y; Wr[q * 4 + 2] = v.z; Wr[q * 4 + 3] = v.w;
    }
    float bias = dtb[d];
    const float* xcp = g_xc + ((size_t)dg * NL + ck * CHUNK) * NC + d;
    float h[NST], ap[NST];
    #pragma unroll
    for (int n = 0; n < NST; n++) { h[n] = 0.0f; ap[n] = 1.0f; }
    for (int t = 0; t < CHUNK; t++) {
        const float* srow = sm + t * 36;
        float s = bias;
        #pragma unroll
        for (int r = 0; r < NRK; r++) s = fmaf(Wr[r], srow[r], s);
        float dl = softplusf(s);
        float u = xcp[(size_t)t * NC];
        float du = dl * u;
        #pragma unroll
        for (int n = 0; n < NST; n++) {
            float a = __expf(dl * A[n]);
            ap[n] *= a;
            h[n] = fmaf(a, h[n], du * srow[NRK + n]);
        }
    }
    float* apO = g_ap   + (((size_t)dg * NCHUNK + ck) * NST) * NC + d;
    float* heO = g_hend + (((size_t)dg * NCHUNK + ck) * NST) * NC + d;
    #pragma unroll
    for (int n = 0; n < NST; n++) { apO[n * NC] = ap[n]; heO[n * NC] = h[n]; }
}

__global__ void __launch_bounds__(256) scan_combine_kernel() {
    int idx = blockIdx.x * 256 + threadIdx.x;
    int d  = idx & (NC - 1);
    int n  = (idx >> 8) & 7;
    int dg = idx >> 11;
    size_t base = ((size_t)dg * NCHUNK * NST + n) * NC + d;
    float h = 0.0f;
    for (int k = 0; k < NCHUNK; k++) {
        size_t o = base + (size_t)k * NST * NC;
        g_hin[o] = h;
        h = g_ap[o] * h + g_hend[o];
    }
}

__global__ void __launch_bounds__(256) scan_pass2_kernel(int dir,
                                                         const float* __restrict__ Wdt,
                                                         const float* __restrict__ dtb,
                                                         const float* __restrict__ Alog,
                                                         const float* __restrict__ Dp) {
    __shared__ float sm[CHUNK * 36];
    const int d  = threadIdx.x;
    const int ck = blockIdx.x;
    const int g  = blockIdx.y;
    const int dg = dir * NG + g;
    {
        const float* xd = g_xdbl + ((size_t)dg * NL + ck * CHUNK) * NEDBL;
        #pragma unroll
        for (int it = 0; it < 4; it++) {
            int flat = threadIdx.x + it * 256;
            int row = flat >> 3, c4 = flat & 7;
            float4 v = *reinterpret_cast<const float4*>(xd + (size_t)row * NEDBL + c4 * 4);
            *reinterpret_cast<float4*>(&sm[row * 36 + c4 * 4]) = v;
        }
    }
    __syncthreads();
    float A[NST];
    #pragma unroll
    for (int n = 0; n < NST; n++) A[n] = -__expf(Alog[d * NST + n]);
    float Wr[NRK];
    #pragma unroll
    for (int q = 0; q < 4; q++) {
        float4 v = *reinterpret_cast<const float4*>(Wdt + d * NRK + q * 4);
        Wr[q * 4] = v.x; Wr[q * 4 + 1] = v.y; Wr[q * 4 + 2] = v.z; Wr[q * 4 + 3] = v.w;
    }
    float bias = dtb[d];
    float Dd = Dp[d];
    const float* xcp = g_xc + ((size_t)dg * NL + ck * CHUNK) * NC + d;
    const float* hiP = g_hin + (((size_t)dg * NCHUNK + ck) * NST) * NC + d;
    float h[NST];
    #pragma unroll
    for (int n = 0; n < NST; n++) h[n] = hiP[n * NC];
    for (int t = 0; t < CHUNK; t++) {
        const float* srow = sm + t * 36;
        float s = bias;
        #pragma unroll
        for (int r = 0; r < NRK; r++) s = fmaf(Wr[r], srow[r], s);
        float dl = softplusf(s);
        float u = xcp[(size_t)t * NC];
        float du = dl * u;
        float accv = 0.0f;
        #pragma unroll
        for (int n = 0; n < NST; n++) {
            float a = __expf(dl * A[n]);
            h[n] = fmaf(a, h[n], du * srow[NRK + n]);
            accv = fmaf(h[n], srow[NRK + NST + n], accv);
        }
        float yv = fmaf(Dd, u, accv);
        int l  = ck * CHUNK + t;
        int lo = dir ? (NL - 1 - l) : l;
        float zv = g_xz[((size_t)g * NL + lo) * (2 * NC) + NC + d];
        float gated = 0.5f * yv * (zv / (1.0f + __expf(-zv)));
        float* yp = g_y + ((size_t)g * NL + lo) * NC + d;
        if (dir == 0) *yp = gated;
        else          *yp += gated;
    }
}

// ---------------------------------------------------------------------------
// final transpose
// ---------------------------------------------------------------------------
__global__ void __launch_bounds__(256) out_transpose_kernel(float* __restrict__ out) {
    __shared__ float tile[32][33];
    int g  = blockIdx.z;
    int c0 = blockIdx.y * 32;
    int l0 = blockIdx.x * 32;
    int tx = threadIdx.x;
    for (int r = threadIdx.y; r < 32; r += 8)
        tile[r][tx] = g_x[((size_t)g * NL + (l0 + r)) * NC + c0 + tx];
    __syncthreads();
    for (int r = threadIdx.y; r < 32; r += 8)
        out[((size_t)g * NC + (c0 + r)) * NL + l0 + tx] = tile[tx][r];
}

// ---------------------------------------------------------------------------
// Launch
// ---------------------------------------------------------------------------
extern "C" void kernel_launch(void* const* d_in, const int* in_sizes, int n_in,
                              void* d_out, int out_size) {
    const float* data       = (const float*)d_in[0];
    const float* ln_w       = (const float*)d_in[1];
    const float* ln_b       = (const float*)d_in[2];
    const float* in_proj_w  = (const float*)d_in[3];
    const float* conv_w     = (const float*)d_in[4];
    const float* conv_b     = (const float*)d_in[5];
    const float* x_proj_w   = (const float*)d_in[6];
    const float* dt_proj_w  = (const float*)d_in[7];
    const float* dt_proj_b  = (const float*)d_in[8];
    const float* A_log      = (const float*)d_in[9];
    const float* A_b_log    = (const float*)d_in[10];
    const float* Dparam     = (const float*)d_in[11];
    const float* out_proj_w = (const float*)d_in[12];
    const float* mn_w       = (const float*)d_in[13];
    const float* mn_b       = (const float*)d_in[14];
    const int*   record_len = (const int*)d_in[15];
    float* out = (float*)d_out;

    float* d_xc;  cudaGetSymbolAddress((void**)&d_xc,  g_xc);
    float* d_xz;  cudaGetSymbolAddress((void**)&d_xz,  g_xz);
    float* d_xdbl;cudaGetSymbolAddress((void**)&d_xdbl,g_xdbl);
    float* d_y;   cudaGetSymbolAddress((void**)&d_y,   g_y);
    float* d_gl;  cudaGetSymbolAddress((void**)&d_gl,  g_gl);
    __nv_bfloat16 *d_xnh, *d_xnl, *d_wih, *d_wil, *d_wxh, *d_wxl, *d_woh, *d_wol;
    cudaGetSymbolAddress((void**)&d_xnh, g_xnh);
    cudaGetSymbolAddress((void**)&d_xnl, g_xnl);
    cudaGetSymbolAddress((void**)&d_wih, g_wih);
    cudaGetSymbolAddress((void**)&d_wil, g_wil);
    cudaGetSymbolAddress((void**)&d_wxh, g_wxh);
    cudaGetSymbolAddress((void**)&d_wxl, g_wxl);
    cudaGetSymbolAddress((void**)&d_woh, g_woh);
    cudaGetSymbolAddress((void**)&d_wol, g_wol);

    // split all weights once per launch
    wsplit_kernel<<<(NDEPTH * 512 * NC + 255) / 256, 256>>>(in_proj_w,  d_wih, d_wil, NDEPTH * 512 * NC);
    wsplit_kernel<<<(NDEPTH * NEDBL * NC + 255) / 256, 256>>>(x_proj_w,  d_wxh, d_wxl, NDEPTH * NEDBL * NC);
    wsplit_kernel<<<(NDEPTH * NC * NC + 255) / 256, 256>>>(out_proj_w, d_woh, d_wol, NDEPTH * NC * NC);

    mean_kernel<<<dim3(NL / 32, NC / 32, NG), dim3(32, 8)>>>(data, record_len);

    for (int i = 0; i < NDEPTH; i++) {
        ln1_kernel<<<NG * NL / 8, 256>>>(ln_w + i * NC, ln_b + i * NC);
        gemm_mma<128, false><<<dim3(NL / 128, 4, NG), 256>>>(
            d_xnh, d_xnl, d_wih + (size_t)i * 512 * NC, d_wil + (size_t)i * 512 * NC, d_xz, 512);
        conv_silu_kernel<<<dim3(NL / 8, 2 * NG), 256>>>(conv_w + i * NC * 4, conv_b + i * NC);
        gemm_mma<32, true><<<dim3(NL / 128, 1, 2 * NG), 256>>>(
            d_xc, nullptr, d_wxh + (size_t)i * NEDBL * NC, d_wxl + (size_t)i * NEDBL * NC, d_xdbl, NEDBL);
        scan_pass1_kernel<<<dim3(NCHUNK, 2 * NG), 256>>>(
            dt_proj_w + (size_t)i * NC * NRK, dt_proj_b + i * NC,
            A_log + (size_t)i * NC * NST, A_b_log + (size_t)i * NC * NST);
        scan_combine_kernel<<<(2 * NG * NST * NC) / 256, 256>>>();
        scan_pass2_kernel<<<dim3(NCHUNK, NG), 256>>>(0,
            dt_proj_w + (size_t)i * NC * NRK, dt_proj_b + i * NC,
            A_log + (size_t)i * NC * NST, Dparam + i * NC);
        scan_pass2_kernel<<<dim3(NCHUNK, NG), 256>>>(1,
            dt_proj_w + (size_t)i * NC * NRK, dt_proj_b + i * NC,
            A_b_log + (size_t)i * NC * NST, Dparam + i * NC);
        gemm_mma<128, true><<<dim3(NL / 128, 2, NG), 256>>>(
            d_y, nullptr, d_woh + (size_t)i * NC * NC, d_wol + (size_t)i * NC * NC, d_gl, 256);
        ln2_kernel<<<NG * NL / 8, 256>>>(mn_w + i * NC, mn_b + i * NC);
    }

    out_transpose_kernel<<<dim3(NL / 32, NC / 32, NG), dim3(32, 8)>>>(out);
}

// round 5
// speedup vs baseline: 3.2805x; 1.0834x over previous
#include <cuda_runtime.h>
#include <cuda_bf16.h>
#include <math.h>
#include <stdint.h>

// ---------------------------------------------------------------------------
// Problem constants
// ---------------------------------------------------------------------------
#define NG     8
#define NC     256
#define NL     4096
#define NST    8
#define NRK    16
#define NEDBL  32
#define NCHUNK 32
#define CHUNK  128
#define NDEPTH 4

// ---------------------------------------------------------------------------
// Scratch
// ---------------------------------------------------------------------------
__device__ float g_x   [NG * NL * NC];            // residual stream (g,l,c)
__device__ float g_xz  [NG * NL * 2 * NC];        // in_proj out [xx|z]
__device__ float g_xdbl[2 * NG * NL * NEDBL];     // x_proj out (dt|B|C)
__device__ float g_y0  [NG * NL * NC];            // fwd raw scan out
__device__ float g_y1  [NG * NL * NC];            // bwd raw scan out
__device__ float g_gl  [NG * NL * NC];            // out_proj out
__device__ float g_ap  [2 * NG * NCHUNK * NST * NC];
__device__ float g_hend[2 * NG * NCHUNK * NST * NC];
__device__ float g_hin [2 * NG * NCHUNK * NST * NC];
__device__ __nv_bfloat16 g_xnh[NG * NL * NC], g_xnl[NG * NL * NC];    // ln1 split
__device__ __nv_bfloat16 g_xch[2 * NG * NL * NC], g_xcl[2 * NG * NL * NC]; // conv split
__device__ __nv_bfloat16 g_wih[NDEPTH * 512 * NC], g_wil[NDEPTH * 512 * NC];
__device__ __nv_bfloat16 g_wxh[NDEPTH * NEDBL * NC], g_wxl[NDEPTH * NEDBL * NC];
__device__ __nv_bfloat16 g_woh[NDEPTH * NC * NC], g_wol[NDEPTH * NC * NC];

// ---------------------------------------------------------------------------
// Helpers
// ---------------------------------------------------------------------------
__device__ __forceinline__ uint32_t smem_u32(const void* p) {
    uint32_t a;
    asm("{ .reg .u64 t; cvta.to.shared.u64 t, %1; cvt.u32.u64 %0, t; }" : "=r"(a) : "l"(p));
    return a;
}
__device__ __forceinline__ uint32_t pack2(__nv_bfloat16 a, __nv_bfloat16 b) {
    __nv_bfloat162 t(a, b);
    return *reinterpret_cast<uint32_t*>(&t);
}
__device__ __forceinline__ void bsplit(float v, __nv_bfloat16& h, __nv_bfloat16& l) {
    h = __float2bfloat16(v);
    l = __float2bfloat16(v - __bfloat162float(h));
}
__device__ __forceinline__ void cp16(uint32_t dst, const void* src) {
    asm volatile("cp.async.cg.shared.global [%0], [%1], 16;" :: "r"(dst), "l"(src));
}
__device__ __forceinline__ void cp_commit() {
    asm volatile("cp.async.commit_group;" ::: "memory");
}
__device__ __forceinline__ void cp_wait1() {
    asm volatile("cp.async.wait_group 1;" ::: "memory");
}
__device__ __forceinline__ void ldsm_x4(uint32_t& r0, uint32_t& r1, uint32_t& r2,
                                        uint32_t& r3, uint32_t addr) {
    asm volatile("ldmatrix.sync.aligned.m8n8.x4.shared.b16 {%0,%1,%2,%3}, [%4];"
                 : "=r"(r0), "=r"(r1), "=r"(r2), "=r"(r3) : "r"(addr));
}
__device__ __forceinline__ void ldsm_x2(uint32_t& r0, uint32_t& r1, uint32_t addr) {
    asm volatile("ldmatrix.sync.aligned.m8n8.x2.shared.b16 {%0,%1}, [%2];"
                 : "=r"(r0), "=r"(r1) : "r"(addr));
}
__device__ __forceinline__ void mma_bf16(float* d, const uint32_t* a, const uint32_t* b) {
    asm volatile("mma.sync.aligned.m16n8k16.row.col.f32.bf16.bf16.f32 "
                 "{%0,%1,%2,%3}, {%4,%5,%6,%7}, {%8,%9}, {%0,%1,%2,%3};"
                 : "+f"(d[0]), "+f"(d[1]), "+f"(d[2]), "+f"(d[3])
                 : "r"(a[0]), "r"(a[1]), "r"(a[2]), "r"(a[3]), "r"(b[0]), "r"(b[1]));
}

// ---------------------------------------------------------------------------
// Weight split (fp32 -> bf16 hi/lo), once per launch
// ---------------------------------------------------------------------------
__global__ void __launch_bounds__(256) wsplit_kernel(const float* __restrict__ w,
                                                     __nv_bfloat16* __restrict__ h,
                                                     __nv_bfloat16* __restrict__ l, int n) {
    int i = blockIdx.x * 256 + threadIdx.x;
    if (i < n) {
        __nv_bfloat16 hh, ll;
        bsplit(w[i], hh, ll);
        h[i] = hh; l[i] = ll;
    }
}

// ---------------------------------------------------------------------------
// Segment mean + transpose
// ---------------------------------------------------------------------------
__global__ void __launch_bounds__(256) mean_kernel(const float* __restrict__ data,
                                                   const int* __restrict__ rl) {
    __shared__ float tile[32][33];
    int g  = blockIdx.z;
    int c0 = blockIdx.y * 32;
    int l0 = blockIdx.x * 32;
    int start = 0;
    for (int gg = 0; gg < g; gg++) start += rl[gg];
    int cnt = rl[g];
    float inv = 1.0f / (float)cnt;
    int tx = threadIdx.x;
    for (int r = threadIdx.y; r < 32; r += 8) {
        float s = 0.0f;
        for (int a = 0; a < cnt; a++)
            s += data[((size_t)(start + a) * NC + (c0 + r)) * NL + l0 + tx];
        tile[r][tx] = s * inv;
    }
    __syncthreads();
    for (int r = threadIdx.y; r < 32; r += 8)
        g_x[((size_t)g * NL + (l0 + r)) * NC + c0 + tx] = tile[tx][r];
}

// ---------------------------------------------------------------------------
// LayerNorm
// ---------------------------------------------------------------------------
__device__ __forceinline__ void warp_stats8(const float* o, float& mu, float& rstd) {
    float s = 0.f, s2 = 0.f;
    #pragma unroll
    for (int i = 0; i < 8; i++) { s += o[i]; s2 += o[i] * o[i]; }
    #pragma unroll
    for (int off = 16; off; off >>= 1) {
        s  += __shfl_xor_sync(0xffffffffu, s, off);
        s2 += __shfl_xor_sync(0xffffffffu, s2, off);
    }
    mu = s * (1.0f / NC);
    float var = s2 * (1.0f / NC) - mu * mu;
    rstd = rsqrtf(var + 1e-5f);
}

// LN1 standalone (layer 0): g_x -> xnh/xnl
__global__ void __launch_bounds__(256) ln1_kernel(const float* __restrict__ w,
                                                  const float* __restrict__ b) {
    int row  = blockIdx.x * 8 + (threadIdx.x >> 5);
    int lane = threadIdx.x & 31;
    const float* xr = g_x + (size_t)row * NC + lane * 8;
    float v[8];
    *reinterpret_cast<float4*>(&v[0]) = *(const float4*)(xr);
    *reinterpret_cast<float4*>(&v[4]) = *(const float4*)(xr + 4);
    float mu, rstd;
    warp_stats8(v, mu, rstd);
    __nv_bfloat16 hh[8], ll[8];
    #pragma unroll
    for (int i = 0; i < 8; i++) {
        float o = (v[i] - mu) * rstd * w[lane * 8 + i] + b[lane * 8 + i];
        bsplit(o, hh[i], ll[i]);
    }
    uint4 vh = {pack2(hh[0],hh[1]), pack2(hh[2],hh[3]), pack2(hh[4],hh[5]), pack2(hh[6],hh[7])};
    uint4 vl = {pack2(ll[0],ll[1]), pack2(ll[2],ll[3]), pack2(ll[4],ll[5]), pack2(ll[6],ll[7])};
    *reinterpret_cast<uint4*>(g_xnh + (size_t)row * NC + lane * 8) = vh;
    *reinterpret_cast<uint4*>(g_xnl + (size_t)row * NC + lane * 8) = vl;
}

// Fused: LN2(g_gl)+residual -> g_x, then LN1(next layer) -> xnh/xnl
__global__ void __launch_bounds__(256) ln2ln1_kernel(const float* __restrict__ mw,
                                                     const float* __restrict__ mb,
                                                     const float* __restrict__ lw,
                                                     const float* __restrict__ lb) {
    int row  = blockIdx.x * 8 + (threadIdx.x >> 5);
    int lane = threadIdx.x & 31;
    const float* xr = g_gl + (size_t)row * NC + lane * 8;
    float v[8];
    *reinterpret_cast<float4*>(&v[0]) = *(const float4*)(xr);
    *reinterpret_cast<float4*>(&v[4]) = *(const float4*)(xr + 4);
    float mu, rstd;
    warp_stats8(v, mu, rstd);
    float* srow = g_x + (size_t)row * NC + lane * 8;
    float sk[8];
    *reinterpret_cast<float4*>(&sk[0]) = *(const float4*)(srow);
    *reinterpret_cast<float4*>(&sk[4]) = *(const float4*)(srow + 4);
    float nx[8];
    #pragma unroll
    for (int i = 0; i < 8; i++)
        nx[i] = (v[i] - mu) * rstd * mw[lane * 8 + i] + mb[lane * 8 + i] + sk[i];
    *(float4*)(srow)     = *reinterpret_cast<float4*>(&nx[0]);
    *(float4*)(srow + 4) = *reinterpret_cast<float4*>(&nx[4]);
    float mu2, rstd2;
    warp_stats8(nx, mu2, rstd2);
    __nv_bfloat16 hh[8], ll[8];
    #pragma unroll
    for (int i = 0; i < 8; i++) {
        float o = (nx[i] - mu2) * rstd2 * lw[lane * 8 + i] + lb[lane * 8 + i];
        bsplit(o, hh[i], ll[i]);
    }
    uint4 vh = {pack2(hh[0],hh[1]), pack2(hh[2],hh[3]), pack2(hh[4],hh[5]), pack2(hh[6],hh[7])};
    uint4 vl = {pack2(ll[0],ll[1]), pack2(ll[2],ll[3]), pack2(ll[4],ll[5]), pack2(ll[6],ll[7])};
    *reinterpret_cast<uint4*>(g_xnh + (size_t)row * NC + lane * 8) = vh;
    *reinterpret_cast<uint4*>(g_xnl + (size_t)row * NC + lane * 8) = vl;
}

// LN2 plain (last layer)
__global__ void __launch_bounds__(256) ln2_kernel(const float* __restrict__ w,
                                                  const float* __restrict__ b) {
    int row  = blockIdx.x * 8 + (threadIdx.x >> 5);
    int lane = threadIdx.x & 31;
    const float* xr = g_gl + (size_t)row * NC + lane * 8;
    float v[8];
    *reinterpret_cast<float4*>(&v[0]) = *(const float4*)(xr);
    *reinterpret_cast<float4*>(&v[4]) = *(const float4*)(xr + 4);
    float mu, rstd;
    warp_stats8(v, mu, rstd);
    float* srow = g_x + (size_t)row * NC + lane * 8;
    float sk[8];
    *reinterpret_cast<float4*>(&sk[0]) = *(const float4*)(srow);
    *reinterpret_cast<float4*>(&sk[4]) = *(const float4*)(srow + 4);
    float nx[8];
    #pragma unroll
    for (int i = 0; i < 8; i++)
        nx[i] = (v[i] - mu) * rstd * w[lane * 8 + i] + b[lane * 8 + i] + sk[i];
    *(float4*)(srow)     = *reinterpret_cast<float4*>(&nx[0]);
    *(float4*)(srow + 4) = *reinterpret_cast<float4*>(&nx[4]);
}

// ---------------------------------------------------------------------------
// Pipelined HMMA GEMM (pre-split bf16 A): C = A @ W^T, K=256
//   2-stage cp.async double buffer, dynamic smem.
//   Stage layout (pitch 80B rows): Ah[128][40] | Al[128][40] | Bh[NT][40] | Bl[NT][40]
// ---------------------------------------------------------------------------
template<int NT>
__global__ void __launch_bounds__(256) gemm_pre(const __nv_bfloat16* __restrict__ Ah,
                                                const __nv_bfloat16* __restrict__ Al,
                                                const __nv_bfloat16* __restrict__ Wh,
                                                const __nv_bfloat16* __restrict__ Wl,
                                                float* __restrict__ C, int ldc) {
    constexpr int WN   = (NT == 128) ? 32 : 8;
    constexpr int NSUB = WN / 8;
    constexpr int BOFF = 20480;
    constexpr int STG  = 20480 + 2 * NT * 80;
    extern __shared__ char dsm[];
    const uint32_t sb = smem_u32(dsm);

    const int tid = threadIdx.x, wid = tid >> 5, lane = tid & 31;
    const int l0 = blockIdx.x * 128, n0 = blockIdx.y * NT;
    const size_t aoff = (size_t)blockIdx.z * NL * NC;
    const int wm = (wid & 1) * 64;
    const int wn = (wid >> 1) * WN;
    const int arow = tid >> 1, ahalf = tid & 1;

    float acc[4][NSUB][4];
    #pragma unroll
    for (int mi = 0; mi < 4; mi++)
        #pragma unroll
        for (int ni = 0; ni < NSUB; ni++)
            #pragma unroll
            for (int q = 0; q < 4; q++) acc[mi][ni][q] = 0.0f;

    // stage issue: copy k-chunk kci into buffer buf
    auto issue = [&](int kci, int buf) {
        uint32_t base = sb + buf * STG;
        int kc = kci * 32;
        const __nv_bfloat16* ag = Ah + aoff + (size_t)(l0 + arow) * NC + kc + ahalf * 16;
        const __nv_bfloat16* alg = Al + aoff + (size_t)(l0 + arow) * NC + kc + ahalf * 16;
        uint32_t ad = base + arow * 80 + ahalf * 32;
        cp16(ad, ag);            cp16(ad + 16, ag + 8);
        cp16(ad + 10240, alg);   cp16(ad + 10240 + 16, alg + 8);
        if (NT == 128 || tid < NT * 2) {
            int brow = tid >> 1, bhalf = tid & 1;
            const __nv_bfloat16* bg  = Wh + (size_t)(n0 + brow) * NC + kc + bhalf * 16;
            const __nv_bfloat16* blg = Wl + (size_t)(n0 + brow) * NC + kc + bhalf * 16;
            uint32_t bd = base + BOFF + brow * 80 + bhalf * 32;
            cp16(bd, bg);             cp16(bd + 16, bg + 8);
            cp16(bd + NT * 80, blg);  cp16(bd + NT * 80 + 16, blg + 8);
        }
    };

    issue(0, 0);
    cp_commit();

    for (int kci = 0; kci < 8; kci++) {
        int buf = kci & 1;
        if (kci + 1 < 8) issue(kci + 1, buf ^ 1);
        cp_commit();
        cp_wait1();
        __syncthreads();
        uint32_t abase = sb + buf * STG;
        #pragma unroll
        for (int kk = 0; kk < 32; kk += 16) {
            uint32_t ah[4][4], al[4][4];
            #pragma unroll
            for (int mi = 0; mi < 4; mi++) {
                uint32_t ad = abase + (wm + mi * 16 + (lane & 15)) * 80 + (kk + (lane >> 4) * 8) * 2;
                ldsm_x4(ah[mi][0], ah[mi][1], ah[mi][2], ah[mi][3], ad);
                ldsm_x4(al[mi][0], al[mi][1], al[mi][2], al[mi][3], ad + 10240);
            }
            uint32_t bh[NSUB][2], bl[NSUB][2];
            #pragma unroll
            for (int ni = 0; ni < NSUB; ni++) {
                uint32_t bd = abase + BOFF + (wn + ni * 8 + (lane & 7)) * 80 + (kk + ((lane >> 3) & 1) * 8) * 2;
                ldsm_x2(bh[ni][0], bh[ni][1], bd);
                ldsm_x2(bl[ni][0], bl[ni][1], bd + NT * 80);
            }
            #pragma unroll
            for (int mi = 0; mi < 4; mi++)
                #pragma unroll
                for (int ni = 0; ni < NSUB; ni++) {
                    mma_bf16(acc[mi][ni], ah[mi], bh[ni]);
                    mma_bf16(acc[mi][ni], ah[mi], bl[ni]);
                    mma_bf16(acc[mi][ni], al[mi], bh[ni]);
                }
        }
        __syncthreads();
    }
    float* Cg = C + (size_t)blockIdx.z * NL * ldc;
    #pragma unroll
    for (int mi = 0; mi < 4; mi++)
        #pragma unroll
        for (int ni = 0; ni < NSUB; ni++) {
            int r = l0 + wm + mi * 16 + (lane >> 2);
            int c = n0 + wn + ni * 8 + (lane & 3) * 2;
            float2 v0 = {acc[mi][ni][0], acc[mi][ni][1]};
            float2 v1 = {acc[mi][ni][2], acc[mi][ni][3]};
            *reinterpret_cast<float2*>(Cg + (size_t)r * ldc + c)       = v0;
            *reinterpret_cast<float2*>(Cg + (size_t)(r + 8) * ldc + c) = v1;
        }
}

// ---------------------------------------------------------------------------
// out_proj GEMM with fused gating: A = 0.5*(y0+y1)*silu(z), split in-kernel.
// ---------------------------------------------------------------------------
__global__ void __launch_bounds__(256) gemm_gated(const float* __restrict__ Y0,
                                                  const float* __restrict__ Y1,
                                                  const float* __restrict__ XZ,
                                                  const __nv_bfloat16* __restrict__ Wh,
                                                  const __nv_bfloat16* __restrict__ Wl,
                                                  float* __restrict__ C, int ldc) {
    __shared__ __nv_bfloat16 Ah_s[128][40];
    __shared__ __nv_bfloat16 Al_s[128][40];
    __shared__ __nv_bfloat16 Bh_s[128][40];
    __shared__ __nv_bfloat16 Bl_s[128][40];

    const int tid = threadIdx.x, wid = tid >> 5, lane = tid & 31;
    const int l0 = blockIdx.x * 128, n0 = blockIdx.y * 128, g = blockIdx.z;
    const int wm = (wid & 1) * 64;
    const int wn = (wid >> 1) * 32;
    const int arow = tid >> 1, ahalf = tid & 1;

    float acc[4][4][4];
    #pragma unroll
    for (int mi = 0; mi < 4; mi++)
        #pragma unroll
        for (int ni = 0; ni < 4; ni++)
            #pragma unroll
            for (int q = 0; q < 4; q++) acc[mi][ni][q] = 0.0f;

    for (int kc = 0; kc < NC; kc += 32) {
        // stage A: gated y
        {
            const float* y0 = Y0 + (size_t)g * NL * NC + (size_t)(l0 + arow) * NC + kc + ahalf * 16;
            const float* y1 = Y1 + (size_t)g * NL * NC + (size_t)(l0 + arow) * NC + kc + ahalf * 16;
            const float* zp = XZ + (size_t)g * NL * 512 + (size_t)(l0 + arow) * 512 + 256 + kc + ahalf * 16;
            float f[16];
            #pragma unroll
            for (int q = 0; q < 4; q++) {
                float4 a0 = *reinterpret_cast<const float4*>(y0 + q * 4);
                float4 a1 = *reinterpret_cast<const float4*>(y1 + q * 4);
                float4 zz = *reinterpret_cast<const float4*>(zp + q * 4);
                f[q*4+0] = 0.5f * (a0.x + a1.x) * (zz.x / (1.0f + __expf(-zz.x)));
                f[q*4+1] = 0.5f * (a0.y + a1.y) * (zz.y / (1.0f + __expf(-zz.y)));
                f[q*4+2] = 0.5f * (a0.z + a1.z) * (zz.z / (1.0f + __expf(-zz.z)));
                f[q*4+3] = 0.5f * (a0.w + a1.w) * (zz.w / (1.0f + __expf(-zz.w)));
            }
            __nv_bfloat16 hh[16], ll[16];
            #pragma unroll
            for (int j = 0; j < 16; j++) bsplit(f[j], hh[j], ll[j]);
            uint4 vh0 = {pack2(hh[0],hh[1]),  pack2(hh[2],hh[3]),  pack2(hh[4],hh[5]),  pack2(hh[6],hh[7])};
            uint4 vh1 = {pack2(hh[8],hh[9]),  pack2(hh[10],hh[11]),pack2(hh[12],hh[13]),pack2(hh[14],hh[15])};
            uint4 vl0 = {pack2(ll[0],ll[1]),  pack2(ll[2],ll[3]),  pack2(ll[4],ll[5]),  pack2(ll[6],ll[7])};
            uint4 vl1 = {pack2(ll[8],ll[9]),  pack2(ll[10],ll[11]),pack2(ll[12],ll[13]),pack2(ll[14],ll[15])};
            *reinterpret_cast<uint4*>(&Ah_s[arow][ahalf * 16])     = vh0;
            *reinterpret_cast<uint4*>(&Ah_s[arow][ahalf * 16 + 8]) = vh1;
            *reinterpret_cast<uint4*>(&Al_s[arow][ahalf * 16])     = vl0;
            *reinterpret_cast<uint4*>(&Al_s[arow][ahalf * 16 + 8]) = vl1;
        }
        // stage B
        {
            const __nv_bfloat16* bg  = Wh + (size_t)(n0 + arow) * NC + kc + ahalf * 16;
            const __nv_bfloat16* blg = Wl + (size_t)(n0 + arow) * NC + kc + ahalf * 16;
            uint4 h0 = *reinterpret_cast<const uint4*>(bg);
            uint4 h1 = *reinterpret_cast<const uint4*>(bg + 8);
            uint4 l0v = *reinterpret_cast<const uint4*>(blg);
            uint4 l1v = *reinterpret_cast<const uint4*>(blg + 8);
            *reinterpret_cast<uint4*>(&Bh_s[arow][ahalf * 16])     = h0;
            *reinterpret_cast<uint4*>(&Bh_s[arow][ahalf * 16 + 8]) = h1;
            *reinterpret_cast<uint4*>(&Bl_s[arow][ahalf * 16])     = l0v;
            *reinterpret_cast<uint4*>(&Bl_s[arow][ahalf * 16 + 8]) = l1v;
        }
        __syncthreads();
        #pragma unroll
        for (int kk = 0; kk < 32; kk += 16) {
            uint32_t ah[4][4], al[4][4];
            #pragma unroll
            for (int mi = 0; mi < 4; mi++) {
                uint32_t ad = smem_u32(&Ah_s[wm + mi * 16 + (lane & 15)][kk + (lane >> 4) * 8]);
                ldsm_x4(ah[mi][0], ah[mi][1], ah[mi][2], ah[mi][3], ad);
                ad = smem_u32(&Al_s[wm + mi * 16 + (lane & 15)][kk + (lane >> 4) * 8]);
                ldsm_x4(al[mi][0], al[mi][1], al[mi][2], al[mi][3], ad);
            }
            uint32_t bh[4][2], bl[4][2];
            #pragma unroll
            for (int ni = 0; ni < 4; ni++) {
                uint32_t bd = smem_u32(&Bh_s[wn + ni * 8 + (lane & 7)][kk + ((lane >> 3) & 1) * 8]);
                ldsm_x2(bh[ni][0], bh[ni][1], bd);
                bd = smem_u32(&Bl_s[wn + ni * 8 + (lane & 7)][kk + ((lane >> 3) & 1) * 8]);
                ldsm_x2(bl[ni][0], bl[ni][1], bd);
            }
            #pragma unroll
            for (int mi = 0; mi < 4; mi++)
                #pragma unroll
                for (int ni = 0; ni < 4; ni++) {
                    mma_bf16(acc[mi][ni], ah[mi], bh[ni]);
                    mma_bf16(acc[mi][ni], ah[mi], bl[ni]);
                    mma_bf16(acc[mi][ni], al[mi], bh[ni]);
                }
        }
        __syncthreads();
    }
    float* Cg = C + (size_t)g * NL * ldc;
    #pragma unroll
    for (int mi = 0; mi < 4; mi++)
        #pragma unroll
        for (int ni = 0; ni < 4; ni++) {
            int r = l0 + wm + mi * 16 + (lane >> 2);
            int c = n0 + wn + ni * 8 + (lane & 3) * 2;
            float2 v0 = {acc[mi][ni][0], acc[mi][ni][1]};
            float2 v1 = {acc[mi][ni][2], acc[mi][ni][3]};
            *reinterpret_cast<float2*>(Cg + (size_t)r * ldc + c)       = v0;
            *reinterpret_cast<float2*>(Cg + (size_t)(r + 8) * ldc + c) = v1;
        }
}

// ---------------------------------------------------------------------------
// conv(k=4 causal) + SiLU -> bf16 hi/lo pair
// ---------------------------------------------------------------------------
__global__ void __launch_bounds__(256) conv_silu_kernel(const float* __restrict__ cw,
                                                        const float* __restrict__ cb) {
    int d  = threadIdx.x;
    int l0 = blockIdx.x * 8;
    int dg = blockIdx.y;
    int dir = dg >> 3, g = dg & 7;
    float4 wv = *reinterpret_cast<const float4*>(cw + d * 4);
    float bias = cb[d];
    const float* X = g_xz + (size_t)g * NL * (2 * NC) + d;
    float x0 = 0.f, x1 = 0.f, x2 = 0.f;
    {
        int lj;
        lj = l0 - 3; if (lj >= 0) x0 = X[(size_t)(dir ? (NL - 1 - lj) : lj) * (2 * NC)];
        lj = l0 - 2; if (lj >= 0) x1 = X[(size_t)(dir ? (NL - 1 - lj) : lj) * (2 * NC)];
        lj = l0 - 1; if (lj >= 0) x2 = X[(size_t)(dir ? (NL - 1 - lj) : lj) * (2 * NC)];
    }
    __nv_bfloat16* oh = g_xch + ((size_t)dg * NL + l0) * NC + d;
    __nv_bfloat16* ol = g_xcl + ((size_t)dg * NL + l0) * NC + d;
    #pragma unroll
    for (int i = 0; i < 8; i++) {
        int l = l0 + i;
        int src = dir ? (NL - 1 - l) : l;
        float x3 = X[(size_t)src * (2 * NC)];
        float s = bias;
        s = fmaf(wv.x, x0, s); s = fmaf(wv.y, x1, s);
        s = fmaf(wv.z, x2, s); s = fmaf(wv.w, x3, s);
        float v = s / (1.0f + __expf(-s));
        __nv_bfloat16 hh, ll;
        bsplit(v, hh, ll);
        oh[(size_t)i * NC] = hh;
        ol[(size_t)i * NC] = ll;
        x0 = x1; x1 = x2; x2 = x3;
    }
}

// ---------------------------------------------------------------------------
// Fused scan (dt_proj + softplus + selective scan)
// ---------------------------------------------------------------------------
__device__ __forceinline__ float softplusf(float s) {
    return (s > 20.0f) ? s : log1pf(__expf(s));
}

__global__ void __launch_bounds__(256) scan_pass1_kernel(const float* __restrict__ Wdt,
                                                         const float* __restrict__ dtb,
                                                         const float* __restrict__ AlogF,
                                                         const float* __restrict__ AlogB) {
    __shared__ float sm[CHUNK * 36];
    const int d  = threadIdx.x;
    const int ck = blockIdx.x;
    const int dg = blockIdx.y;
    const int dir = dg >> 3;
    {
        const float* xd = g_xdbl + ((size_t)dg * NL + ck * CHUNK) * NEDBL;
        #pragma unroll
        for (int it = 0; it < 4; it++) {
            int flat = threadIdx.x + it * 256;
            int row = flat >> 3, c4 = flat & 7;
            float4 v = *reinterpret_cast<const float4*>(xd + (size_t)row * NEDBL + c4 * 4);
            *reinterpret_cast<float4*>(&sm[row * 36 + c4 * 4]) = v;
        }
    }
    __syncthreads();
    const float* Alog = (dir ? AlogB : AlogF) + d * NST;
    float A[NST];
    #pragma unroll
    for (int n = 0; n < NST; n++) A[n] = -__expf(Alog[n]);
    float Wr[NRK];
    #pragma unroll
    for (int q = 0; q < 4; q++) {
        float4 v = *reinterpret_cast<const float4*>(Wdt + d * NRK + q * 4);
        Wr[q * 4] = v.x; Wr[q * 4 + 1] = v.y; Wr[q * 4 + 2] = v.z; Wr[q * 4 + 3] = v.w;
    }
    float bias = dtb[d];
    const __nv_bfloat16* uh = g_xch + ((size_t)dg * NL + ck * CHUNK) * NC + d;
    const __nv_bfloat16* ul = g_xcl + ((size_t)dg * NL + ck * CHUNK) * NC + d;
    float h[NST], ap[NST];
    #pragma unroll
    for (int n = 0; n < NST; n++) { h[n] = 0.0f; ap[n] = 1.0f; }
    for (int t = 0; t < CHUNK; t++) {
        const float* srow = sm + t * 36;
        float s = bias;
        #pragma unroll
        for (int r = 0; r < NRK; r++) s = fmaf(Wr[r], srow[r], s);
        float dl = softplusf(s);
        float u = __bfloat162float(uh[(size_t)t * NC]) + __bfloat162float(ul[(size_t)t * NC]);
        float du = dl * u;
        #pragma unroll
        for (int n = 0; n < NST; n++) {
            float a = __expf(dl * A[n]);
            ap[n] *= a;
            h[n] = fmaf(a, h[n], du * srow[NRK + n]);
        }
    }
    float* apO = g_ap   + (((size_t)dg * NCHUNK + ck) * NST) * NC + d;
    float* heO = g_hend + (((size_t)dg * NCHUNK + ck) * NST) * NC + d;
    #pragma unroll
    for (int n = 0; n < NST; n++) { apO[n * NC] = ap[n]; heO[n * NC] = h[n]; }
}

__global__ void __launch_bounds__(256) scan_combine_kernel() {
    int idx = blockIdx.x * 256 + threadIdx.x;
    int d  = idx & (NC - 1);
    int n  = (idx >> 8) & 7;
    int dg = idx >> 11;
    size_t base = ((size_t)dg * NCHUNK * NST + n) * NC + d;
    float h = 0.0f;
    for (int k = 0; k < NCHUNK; k++) {
        size_t o = base + (size_t)k * NST * NC;
        g_hin[o] = h;
        h = g_ap[o] * h + g_hend[o];
    }
}

// pass2: raw y (incl. D*u), per-direction buffer, no gating
__global__ void __launch_bounds__(256) scan_pass2_kernel(int dir,
                                                         const float* __restrict__ Wdt,
                                                         const float* __restrict__ dtb,
                                                         const float* __restrict__ Alog,
                                                         const float* __restrict__ Dp,
                                                         float* __restrict__ Yout) {
    __shared__ float sm[CHUNK * 36];
    const int d  = threadIdx.x;
    const int ck = blockIdx.x;
    const int g  = blockIdx.y;
    const int dg = dir * NG + g;
    {
        const float* xd = g_xdbl + ((size_t)dg * NL + ck * CHUNK) * NEDBL;
        #pragma unroll
        for (int it = 0; it < 4; it++) {
            int flat = threadIdx.x + it * 256;
            int row = flat >> 3, c4 = flat & 7;
            float4 v = *reinterpret_cast<const float4*>(xd + (size_t)row * NEDBL + c4 * 4);
            *reinterpret_cast<float4*>(&sm[row * 36 + c4 * 4]) = v;
        }
    }
    __syncthreads();
    float A[NST];
    #pragma unroll
    for (int n = 0; n < NST; n++) A[n] = -__expf(Alog[d * NST + n]);
    float Wr[NRK];
    #pragma unroll
    for (int q = 0; q < 4; q++) {
        float4 v = *reinterpret_cast<const float4*>(Wdt + d * NRK + q * 4);
        Wr[q * 4] = v.x; Wr[q * 4 + 1] = v.y; Wr[q * 4 + 2] = v.z; Wr[q * 4 + 3] = v.w;
    }
    float bias = dtb[d];
    float Dd = Dp[d];
    const __nv_bfloat16* uh = g_xch + ((size_t)dg * NL + ck * CHUNK) * NC + d;
    const __nv_bfloat16* ul = g_xcl + ((size_t)dg * NL + ck * CHUNK) * NC + d;
    const float* hiP = g_hin + (((size_t)dg * NCHUNK + ck) * NST) * NC + d;
    float h[NST];
    #pragma unroll
    for (int n = 0; n < NST; n++) h[n] = hiP[n * NC];
    for (int t = 0; t < CHUNK; t++) {
        const float* srow = sm + t * 36;
        float s = bias;
        #pragma unroll
        for (int r = 0; r < NRK; r++) s = fmaf(Wr[r], srow[r], s);
        float dl = softplusf(s);
        float u = __bfloat162float(uh[(size_t)t * NC]) + __bfloat162float(ul[(size_t)t * NC]);
        float du = dl * u;
        float accv = 0.0f;
        #pragma unroll
        for (int n = 0; n < NST; n++) {
            float a = __expf(dl * A[n]);
            h[n] = fmaf(a, h[n], du * srow[NRK + n]);
            accv = fmaf(h[n], srow[NRK + NST + n], accv);
        }
        float yv = fmaf(Dd, u, accv);
        int l  = ck * CHUNK + t;
        int lo = dir ? (NL - 1 - l) : l;
        Yout[((size_t)g * NL + lo) * NC + d] = yv;
    }
}

// ---------------------------------------------------------------------------
// final transpose
// ---------------------------------------------------------------------------
__global__ void __launch_bounds__(256) out_transpose_kernel(float* __restrict__ out) {
    __shared__ float tile[32][33];
    int g  = blockIdx.z;
    int c0 = blockIdx.y * 32;
    int l0 = blockIdx.x * 32;
    int tx = threadIdx.x;
    for (int r = threadIdx.y; r < 32; r += 8)
        tile[r][tx] = g_x[((size_t)g * NL + (l0 + r)) * NC + c0 + tx];
    __syncthreads();
    for (int r = threadIdx.y; r < 32; r += 8)
        out[((size_t)g * NC + (c0 + r)) * NL + l0 + tx] = tile[tx][r];
}

// ---------------------------------------------------------------------------
// Launch
// ---------------------------------------------------------------------------
extern "C" void kernel_launch(void* const* d_in, const int* in_sizes, int n_in,
                              void* d_out, int out_size) {
    const float* data       = (const float*)d_in[0];
    const float* ln_w       = (const float*)d_in[1];
    const float* ln_b       = (const float*)d_in[2];
    const float* in_proj_w  = (const float*)d_in[3];
    const float* conv_w     = (const float*)d_in[4];
    const float* conv_b     = (const float*)d_in[5];
    const float* x_proj_w   = (const float*)d_in[6];
    const float* dt_proj_w  = (const float*)d_in[7];
    const float* dt_proj_b  = (const float*)d_in[8];
    const float* A_log      = (const float*)d_in[9];
    const float* A_b_log    = (const float*)d_in[10];
    const float* Dparam     = (const float*)d_in[11];
    const float* out_proj_w = (const float*)d_in[12];
    const float* mn_w       = (const float*)d_in[13];
    const float* mn_b       = (const float*)d_in[14];
    const int*   record_len = (const int*)d_in[15];
    float* out = (float*)d_out;

    float *d_xz, *d_xdbl, *d_y0, *d_y1, *d_gl;
    cudaGetSymbolAddress((void**)&d_xz,  g_xz);
    cudaGetSymbolAddress((void**)&d_xdbl,g_xdbl);
    cudaGetSymbolAddress((void**)&d_y0,  g_y0);
    cudaGetSymbolAddress((void**)&d_y1,  g_y1);
    cudaGetSymbolAddress((void**)&d_gl,  g_gl);
    __nv_bfloat16 *d_xnh, *d_xnl, *d_xch, *d_xcl;
    __nv_bfloat16 *d_wih, *d_wil, *d_wxh, *d_wxl, *d_woh, *d_wol;
    cudaGetSymbolAddress((void**)&d_xnh, g_xnh);
    cudaGetSymbolAddress((void**)&d_xnl, g_xnl);
    cudaGetSymbolAddress((void**)&d_xch, g_xch);
    cudaGetSymbolAddress((void**)&d_xcl, g_xcl);
    cudaGetSymbolAddress((void**)&d_wih, g_wih);
    cudaGetSymbolAddress((void**)&d_wil, g_wil);
    cudaGetSymbolAddress((void**)&d_wxh, g_wxh);
    cudaGetSymbolAddress((void**)&d_wxl, g_wxl);
    cudaGetSymbolAddress((void**)&d_woh, g_woh);
    cudaGetSymbolAddress((void**)&d_wol, g_wol);

    static bool attrs_set = false;
    if (!attrs_set) {
        cudaFuncSetAttribute(gemm_pre<128>, cudaFuncAttributeMaxDynamicSharedMemorySize, 81920);
        cudaFuncSetAttribute(gemm_pre<32>,  cudaFuncAttributeMaxDynamicSharedMemorySize, 51200);
        attrs_set = true;
    }

    wsplit_kernel<<<(NDEPTH * 512 * NC + 255) / 256, 256>>>(in_proj_w,  d_wih, d_wil, NDEPTH * 512 * NC);
    wsplit_kernel<<<(NDEPTH * NEDBL * NC + 255) / 256, 256>>>(x_proj_w,  d_wxh, d_wxl, NDEPTH * NEDBL * NC);
    wsplit_kernel<<<(NDEPTH * NC * NC + 255) / 256, 256>>>(out_proj_w, d_woh, d_wol, NDEPTH * NC * NC);

    mean_kernel<<<dim3(NL / 32, NC / 32, NG), dim3(32, 8)>>>(data, record_len);
    ln1_kernel<<<NG * NL / 8, 256>>>(ln_w, ln_b);   // layer 0

    for (int i = 0; i < NDEPTH; i++) {
        gemm_pre<128><<<dim3(NL / 128, 4, NG), 256, 81920>>>(
            d_xnh, d_xnl, d_wih + (size_t)i * 512 * NC, d_wil + (size_t)i * 512 * NC, d_xz, 512);
        conv_silu_kernel<<<dim3(NL / 8, 2 * NG), 256>>>(conv_w + i * NC * 4, conv_b + i * NC);
        gemm_pre<32><<<dim3(NL / 128, 1, 2 * NG), 256, 51200>>>(
            d_xch, d_xcl, d_wxh + (size_t)i * NEDBL * NC, d_wxl + (size_t)i * NEDBL * NC, d_xdbl, NEDBL);
        scan_pass1_kernel<<<dim3(NCHUNK, 2 * NG), 256>>>(
            dt_proj_w + (size_t)i * NC * NRK, dt_proj_b + i * NC,
            A_log + (size_t)i * NC * NST, A_b_log + (size_t)i * NC * NST);
        scan_combine_kernel<<<(2 * NG * NST * NC) / 256, 256>>>();
        scan_pass2_kernel<<<dim3(NCHUNK, NG), 256>>>(0,
            dt_proj_w + (size_t)i * NC * NRK, dt_proj_b + i * NC,
            A_log + (size_t)i * NC * NST, Dparam + i * NC, d_y0);
        scan_pass2_kernel<<<dim3(NCHUNK, NG), 256>>>(1,
            dt_proj_w + (size_t)i * NC * NRK, dt_proj_b + i * NC,
            A_b_log + (size_t)i * NC * NST, Dparam + i * NC, d_y1);
        gemm_gated<<<dim3(NL / 128, 2, NG), 256>>>(
            d_y0, d_y1, d_xz, d_woh + (size_t)i * NC * NC, d_wol + (size_t)i * NC * NC, d_gl, 256);
        if (i < NDEPTH - 1)
            ln2ln1_kernel<<<NG * NL / 8, 256>>>(mn_w + i * NC, mn_b + i * NC,
                                                ln_w + (i + 1) * NC, ln_b + (i + 1) * NC);
        else
            ln2_kernel<<<NG * NL / 8, 256>>>(mn_w + i * NC, mn_b + i * NC);
    }

    out_transpose_kernel<<<dim3(NL / 32, NC / 32, NG), dim3(32, 8)>>>(out);
}